// round 5
// baseline (speedup 1.0000x reference)
#include <cuda_runtime.h>
#include <cuda_bf16.h>
#include <math.h>
#include <stdint.h>

#define BATCH 4096
#define FDIM  512
#define NJ    16
#define NM    64
#define NU    512
#define JM    (NJ*NM)   // 1024

// ---- scratch (device globals; no allocation allowed) ----
__device__ __nv_bfloat16 g_hb[(size_t)BATCH * FDIM];   // 4 MB
__device__ __nv_bfloat16 g_db[(size_t)JM * FDIM];      // 1 MB
__device__ __nv_bfloat16 g_Wb[(size_t)JM * NU];        // 1 MB
__device__ __nv_bfloat16 g_A2[(size_t)BATCH * JM];     // 8 MB : e-scaled Khd
__device__ float g_h2[BATCH];
__device__ float g_d2[JM];
__device__ float g_kdd[NJ];
__device__ float g_e[BATCH * NJ];
__device__ float g_Z[BATCH];

// ================= PTX helpers =================
__device__ __forceinline__ void cp16(uint32_t dst, const void* src) {
    asm volatile("cp.async.cg.shared.global [%0], [%1], 16;\n" :: "r"(dst), "l"(src));
}
__device__ __forceinline__ void cp_commit() { asm volatile("cp.async.commit_group;\n"); }
template <int N> __device__ __forceinline__ void cp_wait() {
    asm volatile("cp.async.wait_group %0;\n" :: "n"(N));
}
__device__ __forceinline__ void ldm_x4(uint32_t a[4], uint32_t addr) {
    asm volatile("ldmatrix.sync.aligned.m8n8.x4.shared.b16 {%0,%1,%2,%3}, [%4];\n"
                 : "=r"(a[0]), "=r"(a[1]), "=r"(a[2]), "=r"(a[3]) : "r"(addr));
}
__device__ __forceinline__ void ldm_x4t(uint32_t a[4], uint32_t addr) {
    asm volatile("ldmatrix.sync.aligned.m8n8.x4.trans.shared.b16 {%0,%1,%2,%3}, [%4];\n"
                 : "=r"(a[0]), "=r"(a[1]), "=r"(a[2]), "=r"(a[3]) : "r"(addr));
}
__device__ __forceinline__ void mma_bf16(float c[4], const uint32_t a[4], uint32_t b0, uint32_t b1) {
    asm volatile(
        "mma.sync.aligned.m16n8k16.row.col.f32.bf16.bf16.f32 "
        "{%0,%1,%2,%3}, {%4,%5,%6,%7}, {%8,%9}, {%0,%1,%2,%3};\n"
        : "+f"(c[0]), "+f"(c[1]), "+f"(c[2]), "+f"(c[3])
        : "r"(a[0]), "r"(a[1]), "r"(a[2]), "r"(a[3]), "r"(b0), "r"(b1));
}

// ================= prep: bf16 convert + row sumsq + zero Z ===============
// warp-per-row: rows [0,B)=h, [B,B+JM)=dom, [B+JM,B+2JM)=W
__global__ void __launch_bounds__(256) prep_kernel(const float* __restrict__ h,
                                                   const float* __restrict__ dom,
                                                   const float* __restrict__ W) {
    int warp = (blockIdx.x << 3) + (threadIdx.x >> 5);
    int lane = threadIdx.x & 31;
    const float* p;
    __nv_bfloat16* dst;
    float* o = nullptr;
    if (warp < BATCH) {
        p = h + (size_t)warp * FDIM; dst = g_hb + (size_t)warp * FDIM; o = &g_h2[warp];
        if (lane == 0) g_Z[warp] = 0.f;
    } else if (warp < BATCH + JM) {
        int r = warp - BATCH;
        p = dom + (size_t)r * FDIM; dst = g_db + (size_t)r * FDIM; o = &g_d2[r];
    } else {
        int r = warp - BATCH - JM;
        p = W + (size_t)r * NU; dst = g_Wb + (size_t)r * NU;
    }
    float s = 0.f;
    #pragma unroll
    for (int i = 0; i < 4; i++) {
        int idx = (lane + i * 32) << 2;
        float4 v = *(const float4*)&p[idx];
        __nv_bfloat162 o0 = __floats2bfloat162_rn(v.x, v.y);
        __nv_bfloat162 o1 = __floats2bfloat162_rn(v.z, v.w);
        uint2 u; u.x = *(uint32_t*)&o0; u.y = *(uint32_t*)&o1;
        *(uint2*)&dst[idx] = u;
        s += v.x*v.x + v.y*v.y + v.z*v.z + v.w*v.w;
    }
    if (o) {
        #pragma unroll
        for (int off = 16; off; off >>= 1) s += __shfl_xor_sync(0xffffffffu, s, off);
        if (lane == 0) *o = s;
    }
}

// ================= kdd via tensor cores ==================================
// One block per j, 128 threads (4 warps). Stage dj[64,512] bf16 in smem,
// G = dj @ dj^T via mma, epilogue: kdd[j] = mean exp(-2*(d2m+d2n-2G)).
__global__ void __launch_bounds__(128) kdd_kernel() {
    extern __shared__ char smem[];
    __shared__ float d2s[NM];
    __shared__ float ws[4];
    const int j = blockIdx.x;
    const int tid = threadIdx.x;
    const int lane = tid & 31, w = tid >> 5;
    uint32_t base = (uint32_t)__cvta_generic_to_shared(smem);

    // stage dj: 64 rows x 64 16B-chunks, XOR-swizzled
    const __nv_bfloat16* dj = g_db + (size_t)j * NM * FDIM;
    #pragma unroll
    for (int i = 0; i < 32; i++) {
        int lin = tid + i * 128;
        int r = lin >> 6, c = lin & 63;
        cp16(base + r * 1024 + ((c ^ (r & 7)) << 4), dj + (size_t)r * FDIM + c * 8);
    }
    cp_commit();
    if (tid < NM) d2s[tid] = g_d2[j * NM + tid];
    cp_wait<0>();
    __syncthreads();

    const int rlo = lane & 15, chi = lane >> 4;
    float acc[8][4] = {};
    #pragma unroll 4
    for (int kk = 0; kk < 32; kk++) {
        int ch = kk * 2 + chi;
        uint32_t a[4], b[4][4];
        {
            int row = w * 16 + rlo;
            ldm_x4(a, base + row * 1024 + ((ch ^ (row & 7)) << 4));
        }
        #pragma unroll
        for (int nb = 0; nb < 4; nb++) {
            int row = nb * 16 + rlo;
            ldm_x4(b[nb], base + row * 1024 + ((ch ^ (row & 7)) << 4));
        }
        #pragma unroll
        for (int nb = 0; nb < 4; nb++) {
            mma_bf16(acc[2*nb],   a, b[nb][0], b[nb][2]);
            mma_bf16(acc[2*nb+1], a, b[nb][1], b[nb][3]);
        }
    }

    // epilogue: exp + full reduce
    const int qr = lane >> 2;
    const int qc = (lane & 3) * 2;
    int m0 = w * 16 + qr;
    float d2a = d2s[m0], d2b = d2s[m0 + 8];
    float s = 0.f;
    #pragma unroll
    for (int nt = 0; nt < 8; nt++) {
        int n = nt * 8 + qc;
        float d2x = d2s[n], d2y = d2s[n + 1];
        float* c = acc[nt];
        s += expf(-2.f * (d2a + d2x - 2.f * c[0]));
        s += expf(-2.f * (d2a + d2y - 2.f * c[1]));
        s += expf(-2.f * (d2b + d2x - 2.f * c[2]));
        s += expf(-2.f * (d2b + d2y - 2.f * c[3]));
    }
    #pragma unroll
    for (int off = 16; off; off >>= 1) s += __shfl_xor_sync(0xffffffffu, s, off);
    if (lane == 0) ws[w] = s;
    __syncthreads();
    if (tid == 0) g_kdd[j] = (ws[0] + ws[1] + ws[2] + ws[3]) * (1.0f / (NM * NM));
}

// ================= GEMM1: A2 = e * exp(4*h.domT - 2*(h2+d2)) =============
// 128x128 tile (=2 full domains), BK=32, 3-stage, 256 thr, 2 CTAs/SM.
__global__ void __launch_bounds__(256, 2) gemm1_kernel() {
    extern __shared__ char smem[];
    __shared__ float jp[128][2];
    __shared__ float es[128][2];
    __shared__ float kddm[2];
    const int tid = threadIdx.x;
    const int lane = tid & 31, wid = tid >> 5;
    const int wm = (wid >> 2) * 64;     // 2 m warps
    const int wn = (wid & 3) * 32;      // 4 n warps
    const int m0 = blockIdx.y * 128;
    const int n0 = blockIdx.x * 128;
    const int j0 = blockIdx.x * 2;

    uint32_t base = (uint32_t)__cvta_generic_to_shared(smem);

    if (tid < 256) { jp[tid >> 1][tid & 1] = 0.f; }
    if (tid < 2) kddm[tid] = g_kdd[j0 + tid];

    const int rlo = lane & 15, chi = lane >> 4;
    int arow[4], asw[4], brow[2], bsw[2];
    #pragma unroll
    for (int im = 0; im < 4; im++) { arow[im] = wm + im * 16 + rlo; asw[im] = (arow[im] >> 1) & 3; }
    #pragma unroll
    for (int ib = 0; ib < 2; ib++) { brow[ib] = wn + ib * 16 + rlo; bsw[ib] = (brow[ib] >> 1) & 3; }

    float acc[4][4][4] = {};

    auto load_stage = [&](int ki, int s) {
        const __nv_bfloat16* ha = g_hb + (size_t)m0 * FDIM + ki * 32;
        const __nv_bfloat16* da = g_db + (size_t)n0 * FDIM + ki * 32;
        uint32_t a_s = base + s * 16384;
        uint32_t b_s = a_s + 8192;
        #pragma unroll
        for (int i = 0; i < 2; i++) {
            int lin = tid + i * 256;
            int r = lin >> 2, c = lin & 3;
            uint32_t off = (uint32_t)(r * 64 + (((c ^ ((r >> 1) & 3))) << 4));
            cp16(a_s + off, ha + (size_t)r * FDIM + c * 8);
            cp16(b_s + off, da + (size_t)r * FDIM + c * 8);
        }
        cp_commit();
    };

    auto compute = [&](int s) {
        uint32_t a_s = base + s * 16384;
        uint32_t b_s = a_s + 8192;
        #pragma unroll
        for (int kk = 0; kk < 2; kk++) {
            int ch = kk * 2 + chi;
            uint32_t a[4][4], b[2][4];
            #pragma unroll
            for (int im = 0; im < 4; im++)
                ldm_x4(a[im], a_s + arow[im] * 64 + ((ch ^ asw[im]) << 4));
            #pragma unroll
            for (int ib = 0; ib < 2; ib++)
                ldm_x4(b[ib], b_s + brow[ib] * 64 + ((ch ^ bsw[ib]) << 4));
            #pragma unroll
            for (int im = 0; im < 4; im++) {
                mma_bf16(acc[im][0], a[im], b[0][0], b[0][2]);
                mma_bf16(acc[im][1], a[im], b[0][1], b[0][3]);
                mma_bf16(acc[im][2], a[im], b[1][0], b[1][2]);
                mma_bf16(acc[im][3], a[im], b[1][1], b[1][3]);
            }
        }
    };

    load_stage(0, 0);
    load_stage(1, 1);
    #pragma unroll 1
    for (int ki = 0; ki < 16; ki++) {
        if (ki < 15) cp_wait<1>(); else cp_wait<0>();
        __syncthreads();
        if (ki + 2 < 16) load_stage(ki + 2, (ki + 2) % 3);
        compute(ki % 3);
    }

    // ---- epilogue: exp, per-(row,j) sums, e, scale, store ----
    const int qr = lane >> 2;
    const int qc = (lane & 3) * 2;
    const int jj = wn >> 6;
    #pragma unroll
    for (int im = 0; im < 4; im++) {
        int r0g = m0 + wm + im * 16 + qr;
        float h2a = g_h2[r0g], h2b = g_h2[r0g + 8];
        float rs0 = 0.f, rs1 = 0.f;
        #pragma unroll
        for (int in = 0; in < 4; in++) {
            int cg = n0 + wn + in * 8 + qc;
            float d2x = g_d2[cg], d2y = g_d2[cg + 1];
            float* c = acc[im][in];
            c[0] = expf(4.f * c[0] - 2.f * (h2a + d2x));
            c[1] = expf(4.f * c[1] - 2.f * (h2a + d2y));
            c[2] = expf(4.f * c[2] - 2.f * (h2b + d2x));
            c[3] = expf(4.f * c[3] - 2.f * (h2b + d2y));
            rs0 += c[0] + c[1];
            rs1 += c[2] + c[3];
        }
        rs0 += __shfl_xor_sync(0xffffffffu, rs0, 1);
        rs0 += __shfl_xor_sync(0xffffffffu, rs0, 2);
        rs1 += __shfl_xor_sync(0xffffffffu, rs1, 1);
        rs1 += __shfl_xor_sync(0xffffffffu, rs1, 2);
        if ((lane & 3) == 0) {
            atomicAdd(&jp[wm + im * 16 + qr][jj], rs0);
            atomicAdd(&jp[wm + im * 16 + qr + 8][jj], rs1);
        }
    }
    __syncthreads();
    if (tid < 256) {
        int rl = tid >> 1, j = tid & 1;
        float jsum = jp[rl][j];
        float e = expf(jsum * (1.0f / 32.0f) - 1.0f - kddm[j]);
        es[rl][j] = e;
        g_e[(m0 + rl) * NJ + j0 + j] = e;
        atomicAdd(&g_Z[m0 + rl], e);
    }
    __syncthreads();
    #pragma unroll
    for (int im = 0; im < 4; im++) {
        int rl = wm + im * 16 + qr;
        int r0g = m0 + rl;
        float e0 = es[rl][jj], e1 = es[rl + 8][jj];
        #pragma unroll
        for (int in = 0; in < 4; in++) {
            int cg = n0 + wn + in * 8 + qc;
            float* c = acc[im][in];
            *(__nv_bfloat162*)&g_A2[(size_t)r0g * JM + cg] =
                __floats2bfloat162_rn(c[0] * e0, c[1] * e0);
            *(__nv_bfloat162*)&g_A2[(size_t)(r0g + 8) * JM + cg] =
                __floats2bfloat162_rn(c[2] * e1, c[3] * e1);
        }
    }
}

// ================= GEMM2: out = (A2 @ W + e @ bvec) / Z ==================
// 128x64 tile, BK=32, 4-stage cp.async, 256 threads (4m x 2n warps), 2 CTAs/SM
__global__ void __launch_bounds__(256, 2) gemm2_kernel(const float* __restrict__ bvec,
                                                       float* __restrict__ out) {
    extern __shared__ char smem[];
    __shared__ __nv_bfloat16 Ae[128][24];
    __shared__ __nv_bfloat16 Be[64][24];
    const int tid = threadIdx.x;
    const int lane = tid & 31, wid = tid >> 5;
    const int wm = (wid >> 1) * 32;
    const int wn = (wid & 1) * 32;
    const int m0 = blockIdx.y * 128;
    const int n0 = blockIdx.x * 64;

    uint32_t base = (uint32_t)__cvta_generic_to_shared(smem);
    uint32_t Bs_base = base + 32768;
    uint32_t Ae_base = (uint32_t)__cvta_generic_to_shared(Ae);
    uint32_t Be_base = (uint32_t)__cvta_generic_to_shared(Be);

    for (int idx = tid; idx < 128 * 16; idx += 256) {
        int rr = idx >> 4, j = idx & 15;
        Ae[rr][j] = __float2bfloat16(g_e[(size_t)(m0 + rr) * NJ + j]);
        if (rr < 64) Be[rr][j] = __float2bfloat16(bvec[(size_t)j * NU + n0 + rr]);
    }

    const int rlo = lane & 15, chi = lane >> 4;
    int arow[2], asw[2];
    #pragma unroll
    for (int im = 0; im < 2; im++) { arow[im] = wm + im * 16 + rlo; asw[im] = (arow[im] >> 1) & 3; }

    float acc[2][4][4] = {};

    auto load_stage = [&](int ki, int s) {
        const __nv_bfloat16* asrc = g_A2 + (size_t)m0 * JM + ki * 32;
        const __nv_bfloat16* bsrc = g_Wb + (size_t)ki * 32 * NU + n0;
        uint32_t a_s = base + s * 8192;
        uint32_t b_s = Bs_base + s * 4096;
        #pragma unroll
        for (int i = 0; i < 2; i++) {
            int lin = tid + i * 256;
            int r = lin >> 2, c = lin & 3;
            cp16(a_s + r * 64 + ((c ^ ((r >> 1) & 3)) << 4),
                 asrc + (size_t)r * JM + c * 8);
        }
        {
            int r = tid >> 3, c = tid & 7;
            cp16(b_s + r * 128 + ((c ^ (r & 7)) << 4),
                 bsrc + (size_t)r * NU + c * 8);
        }
        cp_commit();
    };

    auto compute = [&](int s) {
        uint32_t a_s = base + s * 8192;
        uint32_t b_s = Bs_base + s * 4096;
        #pragma unroll
        for (int kk = 0; kk < 2; kk++) {
            int ch = kk * 2 + chi;
            uint32_t a[2][4], b[2][4];
            #pragma unroll
            for (int im = 0; im < 2; im++)
                ldm_x4(a[im], a_s + arow[im] * 64 + ((ch ^ asw[im]) << 4));
            #pragma unroll
            for (int ib = 0; ib < 2; ib++) {
                int row = kk * 16 + rlo;
                int cb = (wn >> 3) + ib * 2 + chi;
                ldm_x4t(b[ib], b_s + row * 128 + ((cb ^ (row & 7)) << 4));
            }
            #pragma unroll
            for (int im = 0; im < 2; im++) {
                mma_bf16(acc[im][0], a[im], b[0][0], b[0][1]);
                mma_bf16(acc[im][1], a[im], b[0][2], b[0][3]);
                mma_bf16(acc[im][2], a[im], b[1][0], b[1][1]);
                mma_bf16(acc[im][3], a[im], b[1][2], b[1][3]);
            }
        }
    };

    load_stage(0, 0);
    load_stage(1, 1);
    load_stage(2, 2);
    #pragma unroll 1
    for (int ki = 0; ki < 32; ki++) {
        if (ki < 29) cp_wait<2>(); else cp_wait<0>();
        __syncthreads();
        if (ki + 3 < 32) load_stage(ki + 3, (ki + 3) & 3);
        compute(ki & 3);
    }

    // ---- bias fold ----
    {
        uint32_t b[2][4];
        #pragma unroll
        for (int ib = 0; ib < 2; ib++) {
            int row = wn + ib * 16 + rlo;
            ldm_x4(b[ib], Be_base + row * 48 + chi * 16);
        }
        #pragma unroll
        for (int im = 0; im < 2; im++) {
            uint32_t a[4];
            int row = wm + im * 16 + rlo;
            ldm_x4(a, Ae_base + row * 48 + chi * 16);
            mma_bf16(acc[im][0], a, b[0][0], b[0][2]);
            mma_bf16(acc[im][1], a, b[0][1], b[0][3]);
            mma_bf16(acc[im][2], a, b[1][0], b[1][2]);
            mma_bf16(acc[im][3], a, b[1][1], b[1][3]);
        }
    }

    // epilogue: divide by Z, store
    const int qr = lane >> 2;
    const int qc = (lane & 3) * 2;
    #pragma unroll
    for (int im = 0; im < 2; im++) {
        int r0g = m0 + wm + im * 16 + qr;
        float zi0 = 1.0f / g_Z[r0g];
        float zi1 = 1.0f / g_Z[r0g + 8];
        #pragma unroll
        for (int in = 0; in < 4; in++) {
            int cg = n0 + wn + in * 8 + qc;
            float* c = acc[im][in];
            float2 v0 = {c[0] * zi0, c[1] * zi0};
            float2 v1 = {c[2] * zi1, c[3] * zi1};
            *(float2*)&out[(size_t)r0g * NU + cg] = v0;
            *(float2*)&out[(size_t)(r0g + 8) * NU + cg] = v1;
        }
    }
}

// ============================================================
extern "C" void kernel_launch(void* const* d_in, const int* in_sizes, int n_in,
                              void* d_out, int out_size) {
    const float* h    = (const float*)d_in[0];   // [B, F]
    const float* dom  = (const float*)d_in[1];   // [J, M, F]
    const float* W    = (const float*)d_in[2];   // [J, M, U]
    const float* bvec = (const float*)d_in[3];   // [J, U]
    float* out = (float*)d_out;                  // [B, U]

    cudaFuncSetAttribute(kdd_kernel,   cudaFuncAttributeMaxDynamicSharedMemorySize, 65536);
    cudaFuncSetAttribute(gemm1_kernel, cudaFuncAttributeMaxDynamicSharedMemorySize, 49152);
    cudaFuncSetAttribute(gemm2_kernel, cudaFuncAttributeMaxDynamicSharedMemorySize, 49152);

    prep_kernel<<<(BATCH + 2 * JM) / 8, 256>>>(h, dom, W);
    kdd_kernel<<<NJ, 128, 65536>>>();
    gemm1_kernel<<<dim3(JM / 128, BATCH / 128), 256, 49152>>>();
    gemm2_kernel<<<dim3(NU / 64, BATCH / 128), 256, 49152>>>(bvec, out);
}

// round 7
// speedup vs baseline: 1.4495x; 1.4495x over previous
#include <cuda_runtime.h>
#include <cuda_bf16.h>
#include <math.h>
#include <stdint.h>

#define BATCH 4096
#define FDIM  512
#define NJ    16
#define NM    64
#define NU    512
#define JM    (NJ*NM)   // 1024

// ---- scratch (device globals; no allocation allowed) ----
__device__ __nv_bfloat16 g_hb[(size_t)BATCH * FDIM];   // 4 MB
__device__ __nv_bfloat16 g_db[(size_t)JM * FDIM];      // 1 MB
__device__ __nv_bfloat16 g_Wb[(size_t)JM * NU];        // 1 MB
__device__ __nv_bfloat16 g_A2[(size_t)BATCH * JM];     // 8 MB : e-scaled Khd
__device__ float g_h2[BATCH];
__device__ float g_d2[JM];
__device__ float g_kdd[NJ];
__device__ float g_e[BATCH * NJ];
__device__ float g_Z[BATCH];

// ================= PTX helpers =================
__device__ __forceinline__ void cp16(uint32_t dst, const void* src) {
    asm volatile("cp.async.cg.shared.global [%0], [%1], 16;\n" :: "r"(dst), "l"(src));
}
__device__ __forceinline__ void cp_commit() { asm volatile("cp.async.commit_group;\n"); }
template <int N> __device__ __forceinline__ void cp_wait() {
    asm volatile("cp.async.wait_group %0;\n" :: "n"(N));
}
__device__ __forceinline__ void ldm_x4(uint32_t a[4], uint32_t addr) {
    asm volatile("ldmatrix.sync.aligned.m8n8.x4.shared.b16 {%0,%1,%2,%3}, [%4];\n"
                 : "=r"(a[0]), "=r"(a[1]), "=r"(a[2]), "=r"(a[3]) : "r"(addr));
}
__device__ __forceinline__ void ldm_x4t(uint32_t a[4], uint32_t addr) {
    asm volatile("ldmatrix.sync.aligned.m8n8.x4.trans.shared.b16 {%0,%1,%2,%3}, [%4];\n"
                 : "=r"(a[0]), "=r"(a[1]), "=r"(a[2]), "=r"(a[3]) : "r"(addr));
}
__device__ __forceinline__ void mma_bf16(float c[4], const uint32_t a[4], uint32_t b0, uint32_t b1) {
    asm volatile(
        "mma.sync.aligned.m16n8k16.row.col.f32.bf16.bf16.f32 "
        "{%0,%1,%2,%3}, {%4,%5,%6,%7}, {%8,%9}, {%0,%1,%2,%3};\n"
        : "+f"(c[0]), "+f"(c[1]), "+f"(c[2]), "+f"(c[3])
        : "r"(a[0]), "r"(a[1]), "r"(a[2]), "r"(a[3]), "r"(b0), "r"(b1));
}

// ================= prep: bf16 convert + row sumsq + zero Z ===============
// warp-per-row: rows [0,B)=h, [B,B+JM)=dom, [B+JM,B+2JM)=W
__global__ void __launch_bounds__(256) prep_kernel(const float* __restrict__ h,
                                                   const float* __restrict__ dom,
                                                   const float* __restrict__ W) {
    int warp = (blockIdx.x << 3) + (threadIdx.x >> 5);
    int lane = threadIdx.x & 31;
    const float* p;
    __nv_bfloat16* dst;
    float* o = nullptr;
    if (warp < BATCH) {
        p = h + (size_t)warp * FDIM; dst = g_hb + (size_t)warp * FDIM; o = &g_h2[warp];
        if (lane == 0) g_Z[warp] = 0.f;
    } else if (warp < BATCH + JM) {
        int r = warp - BATCH;
        p = dom + (size_t)r * FDIM; dst = g_db + (size_t)r * FDIM; o = &g_d2[r];
    } else {
        int r = warp - BATCH - JM;
        p = W + (size_t)r * NU; dst = g_Wb + (size_t)r * NU;
    }
    float s = 0.f;
    #pragma unroll
    for (int i = 0; i < 4; i++) {
        int idx = (lane + i * 32) << 2;
        float4 v = *(const float4*)&p[idx];
        __nv_bfloat162 o0 = __floats2bfloat162_rn(v.x, v.y);
        __nv_bfloat162 o1 = __floats2bfloat162_rn(v.z, v.w);
        uint2 u; u.x = *(uint32_t*)&o0; u.y = *(uint32_t*)&o1;
        *(uint2*)&dst[idx] = u;
        s += v.x*v.x + v.y*v.y + v.z*v.z + v.w*v.w;
    }
    if (o) {
        #pragma unroll
        for (int off = 16; off; off >>= 1) s += __shfl_xor_sync(0xffffffffu, s, off);
        if (lane == 0) *o = s;
    }
}

// ================= kdd via mma.sync tensor cores =========================
__global__ void __launch_bounds__(128) kdd_kernel() {
    extern __shared__ char smem[];
    __shared__ float d2s[NM];
    __shared__ float ws[4];
    const int j = blockIdx.x;
    const int tid = threadIdx.x;
    const int lane = tid & 31, w = tid >> 5;
    uint32_t base = (uint32_t)__cvta_generic_to_shared(smem);

    const __nv_bfloat16* dj = g_db + (size_t)j * NM * FDIM;
    #pragma unroll
    for (int i = 0; i < 32; i++) {
        int lin = tid + i * 128;
        int r = lin >> 6, c = lin & 63;
        cp16(base + r * 1024 + ((c ^ (r & 7)) << 4), dj + (size_t)r * FDIM + c * 8);
    }
    cp_commit();
    if (tid < NM) d2s[tid] = g_d2[j * NM + tid];
    cp_wait<0>();
    __syncthreads();

    const int rlo = lane & 15, chi = lane >> 4;
    float acc[8][4] = {};
    #pragma unroll 4
    for (int kk = 0; kk < 32; kk++) {
        int ch = kk * 2 + chi;
        uint32_t a[4], b[4][4];
        {
            int row = w * 16 + rlo;
            ldm_x4(a, base + row * 1024 + ((ch ^ (row & 7)) << 4));
        }
        #pragma unroll
        for (int nb = 0; nb < 4; nb++) {
            int row = nb * 16 + rlo;
            ldm_x4(b[nb], base + row * 1024 + ((ch ^ (row & 7)) << 4));
        }
        #pragma unroll
        for (int nb = 0; nb < 4; nb++) {
            mma_bf16(acc[2*nb],   a, b[nb][0], b[nb][2]);
            mma_bf16(acc[2*nb+1], a, b[nb][1], b[nb][3]);
        }
    }
    const int qr = lane >> 2;
    const int qc = (lane & 3) * 2;
    int m0 = w * 16 + qr;
    float d2a = d2s[m0], d2b = d2s[m0 + 8];
    float s = 0.f;
    #pragma unroll
    for (int nt = 0; nt < 8; nt++) {
        int n = nt * 8 + qc;
        float d2x = d2s[n], d2y = d2s[n + 1];
        float* c = acc[nt];
        s += expf(-2.f * (d2a + d2x - 2.f * c[0]));
        s += expf(-2.f * (d2a + d2y - 2.f * c[1]));
        s += expf(-2.f * (d2b + d2x - 2.f * c[2]));
        s += expf(-2.f * (d2b + d2y - 2.f * c[3]));
    }
    #pragma unroll
    for (int off = 16; off; off >>= 1) s += __shfl_xor_sync(0xffffffffu, s, off);
    if (lane == 0) ws[w] = s;
    __syncthreads();
    if (tid == 0) g_kdd[j] = (ws[0] + ws[1] + ws[2] + ws[3]) * (1.0f / (NM * NM));
}

// ================= GEMM1: A2 = e * exp(4*h.domT - 2*(h2+d2)) =============
// 128x128 tile (=2 full domains), BK=32, 3-stage, 256 thr, 2 CTAs/SM.
__global__ void __launch_bounds__(256, 2) gemm1_kernel() {
    extern __shared__ char smem[];
    __shared__ float jp[128][2];
    __shared__ float es[128][2];
    __shared__ float kddm[2];
    const int tid = threadIdx.x;
    const int lane = tid & 31, wid = tid >> 5;
    const int wm = (wid >> 2) * 64;     // 2 m warps
    const int wn = (wid & 3) * 32;      // 4 n warps
    const int m0 = blockIdx.y * 128;
    const int n0 = blockIdx.x * 128;
    const int j0 = blockIdx.x * 2;

    uint32_t base = (uint32_t)__cvta_generic_to_shared(smem);

    if (tid < 256) { jp[tid >> 1][tid & 1] = 0.f; }
    if (tid < 2) kddm[tid] = g_kdd[j0 + tid];

    const int rlo = lane & 15, chi = lane >> 4;
    int arow[4], asw[4], brow[2], bsw[2];
    #pragma unroll
    for (int im = 0; im < 4; im++) { arow[im] = wm + im * 16 + rlo; asw[im] = (arow[im] >> 1) & 3; }
    #pragma unroll
    for (int ib = 0; ib < 2; ib++) { brow[ib] = wn + ib * 16 + rlo; bsw[ib] = (brow[ib] >> 1) & 3; }

    float acc[4][4][4] = {};

    auto load_stage = [&](int ki, int s) {
        const __nv_bfloat16* ha = g_hb + (size_t)m0 * FDIM + ki * 32;
        const __nv_bfloat16* da = g_db + (size_t)n0 * FDIM + ki * 32;
        uint32_t a_s = base + s * 16384;
        uint32_t b_s = a_s + 8192;
        #pragma unroll
        for (int i = 0; i < 2; i++) {
            int lin = tid + i * 256;
            int r = lin >> 2, c = lin & 3;
            uint32_t off = (uint32_t)(r * 64 + (((c ^ ((r >> 1) & 3))) << 4));
            cp16(a_s + off, ha + (size_t)r * FDIM + c * 8);
            cp16(b_s + off, da + (size_t)r * FDIM + c * 8);
        }
        cp_commit();
    };

    auto compute = [&](int s) {
        uint32_t a_s = base + s * 16384;
        uint32_t b_s = a_s + 8192;
        #pragma unroll
        for (int kk = 0; kk < 2; kk++) {
            int ch = kk * 2 + chi;
            uint32_t a[4][4], b[2][4];
            #pragma unroll
            for (int im = 0; im < 4; im++)
                ldm_x4(a[im], a_s + arow[im] * 64 + ((ch ^ asw[im]) << 4));
            #pragma unroll
            for (int ib = 0; ib < 2; ib++)
                ldm_x4(b[ib], b_s + brow[ib] * 64 + ((ch ^ bsw[ib]) << 4));
            #pragma unroll
            for (int im = 0; im < 4; im++) {
                mma_bf16(acc[im][0], a[im], b[0][0], b[0][2]);
                mma_bf16(acc[im][1], a[im], b[0][1], b[0][3]);
                mma_bf16(acc[im][2], a[im], b[1][0], b[1][2]);
                mma_bf16(acc[im][3], a[im], b[1][1], b[1][3]);
            }
        }
    };

    load_stage(0, 0);
    load_stage(1, 1);
    #pragma unroll 1
    for (int ki = 0; ki < 16; ki++) {
        if (ki < 15) cp_wait<1>(); else cp_wait<0>();
        __syncthreads();
        if (ki + 2 < 16) load_stage(ki + 2, (ki + 2) % 3);
        compute(ki % 3);
    }

    // ---- epilogue: exp, per-(row,j) sums, e, scale, store ----
    const int qr = lane >> 2;
    const int qc = (lane & 3) * 2;
    const int jj = wn >> 6;
    #pragma unroll
    for (int im = 0; im < 4; im++) {
        int r0g = m0 + wm + im * 16 + qr;
        float h2a = g_h2[r0g], h2b = g_h2[r0g + 8];
        float rs0 = 0.f, rs1 = 0.f;
        #pragma unroll
        for (int in = 0; in < 4; in++) {
            int cg = n0 + wn + in * 8 + qc;
            float d2x = g_d2[cg], d2y = g_d2[cg + 1];
            float* c = acc[im][in];
            c[0] = expf(4.f * c[0] - 2.f * (h2a + d2x));
            c[1] = expf(4.f * c[1] - 2.f * (h2a + d2y));
            c[2] = expf(4.f * c[2] - 2.f * (h2b + d2x));
            c[3] = expf(4.f * c[3] - 2.f * (h2b + d2y));
            rs0 += c[0] + c[1];
            rs1 += c[2] + c[3];
        }
        rs0 += __shfl_xor_sync(0xffffffffu, rs0, 1);
        rs0 += __shfl_xor_sync(0xffffffffu, rs0, 2);
        rs1 += __shfl_xor_sync(0xffffffffu, rs1, 1);
        rs1 += __shfl_xor_sync(0xffffffffu, rs1, 2);
        if ((lane & 3) == 0) {
            atomicAdd(&jp[wm + im * 16 + qr][jj], rs0);
            atomicAdd(&jp[wm + im * 16 + qr + 8][jj], rs1);
        }
    }
    __syncthreads();
    if (tid < 256) {
        int rl = tid >> 1, j = tid & 1;
        float jsum = jp[rl][j];
        float e = expf(jsum * (1.0f / 32.0f) - 1.0f - kddm[j]);
        es[rl][j] = e;
        g_e[(m0 + rl) * NJ + j0 + j] = e;
        atomicAdd(&g_Z[m0 + rl], e);
    }
    __syncthreads();
    #pragma unroll
    for (int im = 0; im < 4; im++) {
        int rl = wm + im * 16 + qr;
        int r0g = m0 + rl;
        float e0 = es[rl][jj], e1 = es[rl + 8][jj];
        #pragma unroll
        for (int in = 0; in < 4; in++) {
            int cg = n0 + wn + in * 8 + qc;
            float* c = acc[im][in];
            *(__nv_bfloat162*)&g_A2[(size_t)r0g * JM + cg] =
                __floats2bfloat162_rn(c[0] * e0, c[1] * e0);
            *(__nv_bfloat162*)&g_A2[(size_t)(r0g + 8) * JM + cg] =
                __floats2bfloat162_rn(c[2] * e1, c[3] * e1);
        }
    }
}

// ================= GEMM2: out = (A2 @ W + e @ bvec) / Z ==================
// 128x64 tile, BK=64, 3-stage, 128 threads (2m x 2n warps, warp 64x32), 2+ CTAs/SM
__global__ void __launch_bounds__(128, 2) gemm2_kernel(const float* __restrict__ bvec,
                                                       float* __restrict__ out) {
    extern __shared__ char smem[];
    // dynamic layout:
    //   A stages: 3 x 16384 at 0
    //   B stages: 3 x 8192  at 49152
    //   Ae [128][24] bf16 at 73728 (6144 B)
    //   Be [64][24]  bf16 at 79872 (3072 B)
    const int tid = threadIdx.x;
    const int lane = tid & 31, wid = tid >> 5;
    const int wm = (wid >> 1) * 64;    // 2 m bands
    const int wn = (wid & 1) * 32;     // 2 n bands
    const int m0 = blockIdx.y * 128;
    const int n0 = blockIdx.x * 64;

    uint32_t base = (uint32_t)__cvta_generic_to_shared(smem);
    uint32_t Bs_base = base + 49152;
    uint32_t Ae_base = base + 73728;
    uint32_t Be_base = base + 79872;
    __nv_bfloat16* Ae = (__nv_bfloat16*)(smem + 73728);
    __nv_bfloat16* Be = (__nv_bfloat16*)(smem + 79872);

    // stage e (bf16) and bvec^T (bf16)
    for (int idx = tid; idx < 128 * 16; idx += 128) {
        int rr = idx >> 4, j = idx & 15;
        Ae[rr * 24 + j] = __float2bfloat16(g_e[(size_t)(m0 + rr) * NJ + j]);
        if (rr < 64) Be[rr * 24 + j] = __float2bfloat16(bvec[(size_t)j * NU + n0 + rr]);
    }

    const int rlo = lane & 15, chi = lane >> 4;
    int arow[4], asw[4];
    #pragma unroll
    for (int im = 0; im < 4; im++) { arow[im] = wm + im * 16 + rlo; asw[im] = arow[im] & 7; }

    float acc[4][4][4] = {};

    auto load_stage = [&](int ki, int s) {
        const __nv_bfloat16* asrc = g_A2 + (size_t)m0 * JM + ki * 64;
        const __nv_bfloat16* bsrc = g_Wb + (size_t)ki * 64 * NU + n0;
        uint32_t a_s = base + s * 16384;
        uint32_t b_s = Bs_base + s * 8192;
        // A: 128 rows x 8 chunks = 1024 cp16 / 128 thr = 8 each
        #pragma unroll
        for (int i = 0; i < 8; i++) {
            int lin = tid + i * 128;
            int r = lin >> 3, c = lin & 7;
            cp16(a_s + r * 128 + ((c ^ (r & 7)) << 4), asrc + (size_t)r * JM + c * 8);
        }
        // B: 64 rows x 8 chunks = 512 cp16 / 128 thr = 4 each
        #pragma unroll
        for (int i = 0; i < 4; i++) {
            int lin = tid + i * 128;
            int r = lin >> 3, c = lin & 7;
            cp16(b_s + r * 128 + ((c ^ (r & 7)) << 4), bsrc + (size_t)r * NU + c * 8);
        }
        cp_commit();
    };

    auto compute = [&](int s) {
        uint32_t a_s = base + s * 16384;
        uint32_t b_s = Bs_base + s * 8192;
        #pragma unroll
        for (int kk = 0; kk < 4; kk++) {
            int ch = kk * 2 + chi;
            uint32_t a[4][4], b[2][4];
            #pragma unroll
            for (int im = 0; im < 4; im++)
                ldm_x4(a[im], a_s + arow[im] * 128 + ((ch ^ asw[im]) << 4));
            #pragma unroll
            for (int ib = 0; ib < 2; ib++) {
                int row = kk * 16 + rlo;
                int cb = (wn >> 3) + ib * 2 + chi;
                ldm_x4t(b[ib], b_s + row * 128 + ((cb ^ (row & 7)) << 4));
            }
            #pragma unroll
            for (int im = 0; im < 4; im++) {
                mma_bf16(acc[im][0], a[im], b[0][0], b[0][1]);
                mma_bf16(acc[im][1], a[im], b[0][2], b[0][3]);
                mma_bf16(acc[im][2], a[im], b[1][0], b[1][1]);
                mma_bf16(acc[im][3], a[im], b[1][2], b[1][3]);
            }
        }
    };

    load_stage(0, 0);
    load_stage(1, 1);
    #pragma unroll 1
    for (int ki = 0; ki < 16; ki++) {
        if (ki < 15) cp_wait<1>(); else cp_wait<0>();
        __syncthreads();
        if (ki + 2 < 16) load_stage(ki + 2, (ki + 2) % 3);
        compute(ki % 3);
    }

    // ---- bias fold: one extra k16 step with A'=e(bf16), B'=bvec^T ----
    {
        uint32_t b[2][4];
        #pragma unroll
        for (int ib = 0; ib < 2; ib++) {
            int row = wn + ib * 16 + rlo;
            ldm_x4(b[ib], Be_base + row * 48 + chi * 16);
        }
        #pragma unroll
        for (int im = 0; im < 4; im++) {
            uint32_t a[4];
            int row = wm + im * 16 + rlo;
            ldm_x4(a, Ae_base + row * 48 + chi * 16);
            mma_bf16(acc[im][0], a, b[0][0], b[0][2]);
            mma_bf16(acc[im][1], a, b[0][1], b[0][3]);
            mma_bf16(acc[im][2], a, b[1][0], b[1][2]);
            mma_bf16(acc[im][3], a, b[1][1], b[1][3]);
        }
    }

    // epilogue: divide by Z, store
    const int qr = lane >> 2;
    const int qc = (lane & 3) * 2;
    #pragma unroll
    for (int im = 0; im < 4; im++) {
        int r0g = m0 + wm + im * 16 + qr;
        float zi0 = 1.0f / g_Z[r0g];
        float zi1 = 1.0f / g_Z[r0g + 8];
        #pragma unroll
        for (int in = 0; in < 4; in++) {
            int cg = n0 + wn + in * 8 + qc;
            float* c = acc[im][in];
            float2 v0 = {c[0] * zi0, c[1] * zi0};
            float2 v1 = {c[2] * zi1, c[3] * zi1};
            *(float2*)&out[(size_t)r0g * NU + cg] = v0;
            *(float2*)&out[(size_t)(r0g + 8) * NU + cg] = v1;
        }
    }
}

// ============================================================
extern "C" void kernel_launch(void* const* d_in, const int* in_sizes, int n_in,
                              void* d_out, int out_size) {
    const float* h    = (const float*)d_in[0];   // [B, F]
    const float* dom  = (const float*)d_in[1];   // [J, M, F]
    const float* W    = (const float*)d_in[2];   // [J, M, U]
    const float* bvec = (const float*)d_in[3];   // [J, U]
    float* out = (float*)d_out;                  // [B, U]

    cudaFuncSetAttribute(kdd_kernel,   cudaFuncAttributeMaxDynamicSharedMemorySize, 65536);
    cudaFuncSetAttribute(gemm1_kernel, cudaFuncAttributeMaxDynamicSharedMemorySize, 49152);
    cudaFuncSetAttribute(gemm2_kernel, cudaFuncAttributeMaxDynamicSharedMemorySize, 82944);

    prep_kernel<<<(BATCH + 2 * JM) / 8, 256>>>(h, dom, W);
    kdd_kernel<<<NJ, 128, 65536>>>();
    gemm1_kernel<<<dim3(JM / 128, BATCH / 128), 256, 49152>>>();
    gemm2_kernel<<<dim3(NU / 64, BATCH / 128), 128, 82944>>>(bvec, out);
}

// round 8
// speedup vs baseline: 1.5000x; 1.0348x over previous
#include <cuda_runtime.h>
#include <cuda_bf16.h>
#include <math.h>
#include <stdint.h>

#define BATCH 4096
#define FDIM  512
#define NJ    16
#define NM    64
#define NU    512
#define JM    (NJ*NM)   // 1024

// ---- scratch (device globals; no allocation allowed) ----
__device__ __nv_bfloat16 g_hb[(size_t)BATCH * FDIM];   // 4 MB
__device__ __nv_bfloat16 g_db[(size_t)JM * FDIM];      // 1 MB
__device__ __nv_bfloat16 g_Wb[(size_t)JM * NU];        // 1 MB
__device__ __nv_bfloat16 g_A2[(size_t)BATCH * JM];     // 8 MB : e-scaled Khd
__device__ float g_h2[BATCH];
__device__ float g_d2[JM];
__device__ float g_kdd[NJ];
__device__ float g_e[BATCH * NJ];
__device__ float g_Z[BATCH];

// ================= PTX helpers =================
__device__ __forceinline__ void cp16(uint32_t dst, const void* src) {
    asm volatile("cp.async.cg.shared.global [%0], [%1], 16;\n" :: "r"(dst), "l"(src));
}
__device__ __forceinline__ void cp_commit() { asm volatile("cp.async.commit_group;\n"); }
template <int N> __device__ __forceinline__ void cp_wait() {
    asm volatile("cp.async.wait_group %0;\n" :: "n"(N));
}
__device__ __forceinline__ void ldm_x4(uint32_t a[4], uint32_t addr) {
    asm volatile("ldmatrix.sync.aligned.m8n8.x4.shared.b16 {%0,%1,%2,%3}, [%4];\n"
                 : "=r"(a[0]), "=r"(a[1]), "=r"(a[2]), "=r"(a[3]) : "r"(addr));
}
__device__ __forceinline__ void ldm_x4t(uint32_t a[4], uint32_t addr) {
    asm volatile("ldmatrix.sync.aligned.m8n8.x4.trans.shared.b16 {%0,%1,%2,%3}, [%4];\n"
                 : "=r"(a[0]), "=r"(a[1]), "=r"(a[2]), "=r"(a[3]) : "r"(addr));
}
__device__ __forceinline__ void mma_bf16(float c[4], const uint32_t a[4], uint32_t b0, uint32_t b1) {
    asm volatile(
        "mma.sync.aligned.m16n8k16.row.col.f32.bf16.bf16.f32 "
        "{%0,%1,%2,%3}, {%4,%5,%6,%7}, {%8,%9}, {%0,%1,%2,%3};\n"
        : "+f"(c[0]), "+f"(c[1]), "+f"(c[2]), "+f"(c[3])
        : "r"(a[0]), "r"(a[1]), "r"(a[2]), "r"(a[3]), "r"(b0), "r"(b1));
}

// ================= prep: bf16 convert + row sumsq + zero Z ===============
// warp-per-row: rows [0,B)=h, [B,B+JM)=dom, [B+JM,B+2JM)=W
__global__ void __launch_bounds__(256) prep_kernel(const float* __restrict__ h,
                                                   const float* __restrict__ dom,
                                                   const float* __restrict__ W) {
    int warp = (blockIdx.x << 3) + (threadIdx.x >> 5);
    int lane = threadIdx.x & 31;
    const float* p;
    __nv_bfloat16* dst;
    float* o = nullptr;
    if (warp < BATCH) {
        p = h + (size_t)warp * FDIM; dst = g_hb + (size_t)warp * FDIM; o = &g_h2[warp];
        if (lane == 0) g_Z[warp] = 0.f;
    } else if (warp < BATCH + JM) {
        int r = warp - BATCH;
        p = dom + (size_t)r * FDIM; dst = g_db + (size_t)r * FDIM; o = &g_d2[r];
    } else {
        int r = warp - BATCH - JM;
        p = W + (size_t)r * NU; dst = g_Wb + (size_t)r * NU;
    }
    float s = 0.f;
    #pragma unroll
    for (int i = 0; i < 4; i++) {
        int idx = (lane + i * 32) << 2;
        float4 v = *(const float4*)&p[idx];
        __nv_bfloat162 o0 = __floats2bfloat162_rn(v.x, v.y);
        __nv_bfloat162 o1 = __floats2bfloat162_rn(v.z, v.w);
        uint2 u; u.x = *(uint32_t*)&o0; u.y = *(uint32_t*)&o1;
        *(uint2*)&dst[idx] = u;
        s += v.x*v.x + v.y*v.y + v.z*v.z + v.w*v.w;
    }
    if (o) {
        #pragma unroll
        for (int off = 16; off; off >>= 1) s += __shfl_xor_sync(0xffffffffu, s, off);
        if (lane == 0) *o = s;
    }
}

// ================= kdd via mma.sync tensor cores =========================
__global__ void __launch_bounds__(128) kdd_kernel() {
    extern __shared__ char smem[];
    __shared__ float d2s[NM];
    __shared__ float ws[4];
    const int j = blockIdx.x;
    const int tid = threadIdx.x;
    const int lane = tid & 31, w = tid >> 5;
    uint32_t base = (uint32_t)__cvta_generic_to_shared(smem);

    const __nv_bfloat16* dj = g_db + (size_t)j * NM * FDIM;
    #pragma unroll
    for (int i = 0; i < 32; i++) {
        int lin = tid + i * 128;
        int r = lin >> 6, c = lin & 63;
        cp16(base + r * 1024 + ((c ^ (r & 7)) << 4), dj + (size_t)r * FDIM + c * 8);
    }
    cp_commit();
    if (tid < NM) d2s[tid] = g_d2[j * NM + tid];
    cp_wait<0>();
    __syncthreads();

    const int rlo = lane & 15, chi = lane >> 4;
    float acc[8][4] = {};
    #pragma unroll 4
    for (int kk = 0; kk < 32; kk++) {
        int ch = kk * 2 + chi;
        uint32_t a[4], b[4][4];
        {
            int row = w * 16 + rlo;
            ldm_x4(a, base + row * 1024 + ((ch ^ (row & 7)) << 4));
        }
        #pragma unroll
        for (int nb = 0; nb < 4; nb++) {
            int row = nb * 16 + rlo;
            ldm_x4(b[nb], base + row * 1024 + ((ch ^ (row & 7)) << 4));
        }
        #pragma unroll
        for (int nb = 0; nb < 4; nb++) {
            mma_bf16(acc[2*nb],   a, b[nb][0], b[nb][2]);
            mma_bf16(acc[2*nb+1], a, b[nb][1], b[nb][3]);
        }
    }
    const int qr = lane >> 2;
    const int qc = (lane & 3) * 2;
    int m0 = w * 16 + qr;
    float d2a = d2s[m0], d2b = d2s[m0 + 8];
    float s = 0.f;
    #pragma unroll
    for (int nt = 0; nt < 8; nt++) {
        int n = nt * 8 + qc;
        float d2x = d2s[n], d2y = d2s[n + 1];
        float* c = acc[nt];
        s += expf(-2.f * (d2a + d2x - 2.f * c[0]));
        s += expf(-2.f * (d2a + d2y - 2.f * c[1]));
        s += expf(-2.f * (d2b + d2x - 2.f * c[2]));
        s += expf(-2.f * (d2b + d2y - 2.f * c[3]));
    }
    #pragma unroll
    for (int off = 16; off; off >>= 1) s += __shfl_xor_sync(0xffffffffu, s, off);
    if (lane == 0) ws[w] = s;
    __syncthreads();
    if (tid == 0) g_kdd[j] = (ws[0] + ws[1] + ws[2] + ws[3]) * (1.0f / (NM * NM));
}

// ================= GEMM1: A2 = e * exp(4*h.domT - 2*(h2+d2)) =============
// 128x128 tile (=2 full domains), BK=32, 3-stage, 256 thr, 2 CTAs/SM.
__global__ void __launch_bounds__(256, 2) gemm1_kernel() {
    extern __shared__ char smem[];
    __shared__ float jp[128][2];
    __shared__ float es[128][2];
    __shared__ float kddm[2];
    const int tid = threadIdx.x;
    const int lane = tid & 31, wid = tid >> 5;
    const int wm = (wid >> 2) * 64;     // 2 m warps
    const int wn = (wid & 3) * 32;      // 4 n warps
    const int m0 = blockIdx.y * 128;
    const int n0 = blockIdx.x * 128;
    const int j0 = blockIdx.x * 2;

    uint32_t base = (uint32_t)__cvta_generic_to_shared(smem);

    if (tid < 256) { jp[tid >> 1][tid & 1] = 0.f; }
    if (tid < 2) kddm[tid] = g_kdd[j0 + tid];

    const int rlo = lane & 15, chi = lane >> 4;
    int arow[4], asw[4], brow[2], bsw[2];
    #pragma unroll
    for (int im = 0; im < 4; im++) { arow[im] = wm + im * 16 + rlo; asw[im] = (arow[im] >> 1) & 3; }
    #pragma unroll
    for (int ib = 0; ib < 2; ib++) { brow[ib] = wn + ib * 16 + rlo; bsw[ib] = (brow[ib] >> 1) & 3; }

    float acc[4][4][4] = {};

    auto load_stage = [&](int ki, int s) {
        const __nv_bfloat16* ha = g_hb + (size_t)m0 * FDIM + ki * 32;
        const __nv_bfloat16* da = g_db + (size_t)n0 * FDIM + ki * 32;
        uint32_t a_s = base + s * 16384;
        uint32_t b_s = a_s + 8192;
        #pragma unroll
        for (int i = 0; i < 2; i++) {
            int lin = tid + i * 256;
            int r = lin >> 2, c = lin & 3;
            uint32_t off = (uint32_t)(r * 64 + (((c ^ ((r >> 1) & 3))) << 4));
            cp16(a_s + off, ha + (size_t)r * FDIM + c * 8);
            cp16(b_s + off, da + (size_t)r * FDIM + c * 8);
        }
        cp_commit();
    };

    auto compute = [&](int s) {
        uint32_t a_s = base + s * 16384;
        uint32_t b_s = a_s + 8192;
        #pragma unroll
        for (int kk = 0; kk < 2; kk++) {
            int ch = kk * 2 + chi;
            uint32_t a[4][4], b[2][4];
            #pragma unroll
            for (int im = 0; im < 4; im++)
                ldm_x4(a[im], a_s + arow[im] * 64 + ((ch ^ asw[im]) << 4));
            #pragma unroll
            for (int ib = 0; ib < 2; ib++)
                ldm_x4(b[ib], b_s + brow[ib] * 64 + ((ch ^ bsw[ib]) << 4));
            #pragma unroll
            for (int im = 0; im < 4; im++) {
                mma_bf16(acc[im][0], a[im], b[0][0], b[0][2]);
                mma_bf16(acc[im][1], a[im], b[0][1], b[0][3]);
                mma_bf16(acc[im][2], a[im], b[1][0], b[1][2]);
                mma_bf16(acc[im][3], a[im], b[1][1], b[1][3]);
            }
        }
    };

    load_stage(0, 0);
    load_stage(1, 1);
    #pragma unroll 1
    for (int ki = 0; ki < 16; ki++) {
        if (ki < 15) cp_wait<1>(); else cp_wait<0>();
        __syncthreads();
        if (ki + 2 < 16) load_stage(ki + 2, (ki + 2) % 3);
        compute(ki % 3);
    }

    // ---- epilogue: exp, per-(row,j) sums, e, scale, store ----
    const int qr = lane >> 2;
    const int qc = (lane & 3) * 2;
    const int jj = wn >> 6;
    #pragma unroll
    for (int im = 0; im < 4; im++) {
        int r0g = m0 + wm + im * 16 + qr;
        float h2a = g_h2[r0g], h2b = g_h2[r0g + 8];
        float rs0 = 0.f, rs1 = 0.f;
        #pragma unroll
        for (int in = 0; in < 4; in++) {
            int cg = n0 + wn + in * 8 + qc;
            float d2x = g_d2[cg], d2y = g_d2[cg + 1];
            float* c = acc[im][in];
            c[0] = expf(4.f * c[0] - 2.f * (h2a + d2x));
            c[1] = expf(4.f * c[1] - 2.f * (h2a + d2y));
            c[2] = expf(4.f * c[2] - 2.f * (h2b + d2x));
            c[3] = expf(4.f * c[3] - 2.f * (h2b + d2y));
            rs0 += c[0] + c[1];
            rs1 += c[2] + c[3];
        }
        rs0 += __shfl_xor_sync(0xffffffffu, rs0, 1);
        rs0 += __shfl_xor_sync(0xffffffffu, rs0, 2);
        rs1 += __shfl_xor_sync(0xffffffffu, rs1, 1);
        rs1 += __shfl_xor_sync(0xffffffffu, rs1, 2);
        if ((lane & 3) == 0) {
            atomicAdd(&jp[wm + im * 16 + qr][jj], rs0);
            atomicAdd(&jp[wm + im * 16 + qr + 8][jj], rs1);
        }
    }
    __syncthreads();
    if (tid < 256) {
        int rl = tid >> 1, j = tid & 1;
        float jsum = jp[rl][j];
        float e = expf(jsum * (1.0f / 32.0f) - 1.0f - kddm[j]);
        es[rl][j] = e;
        g_e[(m0 + rl) * NJ + j0 + j] = e;
        atomicAdd(&g_Z[m0 + rl], e);
    }
    __syncthreads();
    #pragma unroll
    for (int im = 0; im < 4; im++) {
        int rl = wm + im * 16 + qr;
        int r0g = m0 + rl;
        float e0 = es[rl][jj], e1 = es[rl + 8][jj];
        #pragma unroll
        for (int in = 0; in < 4; in++) {
            int cg = n0 + wn + in * 8 + qc;
            float* c = acc[im][in];
            *(__nv_bfloat162*)&g_A2[(size_t)r0g * JM + cg] =
                __floats2bfloat162_rn(c[0] * e0, c[1] * e0);
            *(__nv_bfloat162*)&g_A2[(size_t)(r0g + 8) * JM + cg] =
                __floats2bfloat162_rn(c[2] * e1, c[3] * e1);
        }
    }
}

// ================= GEMM2: out = (A2 @ W + e @ bvec) / Z ==================
// 128x64 tile, BK=64, 3-stage, 256 threads (4m x 2n warps, warp 32x32), 2 CTAs/SM
__global__ void __launch_bounds__(256, 2) gemm2_kernel(const float* __restrict__ bvec,
                                                       float* __restrict__ out) {
    extern __shared__ char smem[];
    // dynamic layout:
    //   A stages: 3 x 16384 at 0
    //   B stages: 3 x 8192  at 49152
    //   Ae [128][24] bf16 at 73728 (6144 B)
    //   Be [64][24]  bf16 at 79872 (3072 B)
    const int tid = threadIdx.x;
    const int lane = tid & 31, wid = tid >> 5;
    const int wm = (wid >> 1) * 32;    // 4 m bands of 32
    const int wn = (wid & 1) * 32;     // 2 n bands of 32
    const int m0 = blockIdx.y * 128;
    const int n0 = blockIdx.x * 64;

    uint32_t base = (uint32_t)__cvta_generic_to_shared(smem);
    uint32_t Bs_base = base + 49152;
    uint32_t Ae_base = base + 73728;
    uint32_t Be_base = base + 79872;
    __nv_bfloat16* Ae = (__nv_bfloat16*)(smem + 73728);
    __nv_bfloat16* Be = (__nv_bfloat16*)(smem + 79872);

    // stage e (bf16) and bvec^T (bf16)
    for (int idx = tid; idx < 128 * 16; idx += 256) {
        int rr = idx >> 4, j = idx & 15;
        Ae[rr * 24 + j] = __float2bfloat16(g_e[(size_t)(m0 + rr) * NJ + j]);
        if (rr < 64) Be[rr * 24 + j] = __float2bfloat16(bvec[(size_t)j * NU + n0 + rr]);
    }

    const int rlo = lane & 15, chi = lane >> 4;
    int arow[2], asw[2];
    #pragma unroll
    for (int im = 0; im < 2; im++) { arow[im] = wm + im * 16 + rlo; asw[im] = arow[im] & 7; }

    float acc[2][4][4] = {};

    auto load_stage = [&](int ki, int s) {
        const __nv_bfloat16* asrc = g_A2 + (size_t)m0 * JM + ki * 64;
        const __nv_bfloat16* bsrc = g_Wb + (size_t)ki * 64 * NU + n0;
        uint32_t a_s = base + s * 16384;
        uint32_t b_s = Bs_base + s * 8192;
        // A: 128 rows x 8 chunks = 1024 cp16 / 256 thr = 4 each
        #pragma unroll
        for (int i = 0; i < 4; i++) {
            int lin = tid + i * 256;
            int r = lin >> 3, c = lin & 7;
            cp16(a_s + r * 128 + ((c ^ (r & 7)) << 4), asrc + (size_t)r * JM + c * 8);
        }
        // B: 64 rows x 8 chunks = 512 cp16 / 256 thr = 2 each
        #pragma unroll
        for (int i = 0; i < 2; i++) {
            int lin = tid + i * 256;
            int r = lin >> 3, c = lin & 7;
            cp16(b_s + r * 128 + ((c ^ (r & 7)) << 4), bsrc + (size_t)r * NU + c * 8);
        }
        cp_commit();
    };

    auto compute = [&](int s) {
        uint32_t a_s = base + s * 16384;
        uint32_t b_s = Bs_base + s * 8192;
        #pragma unroll
        for (int kk = 0; kk < 4; kk++) {
            int ch = kk * 2 + chi;
            uint32_t a[2][4], b[2][4];
            #pragma unroll
            for (int im = 0; im < 2; im++)
                ldm_x4(a[im], a_s + arow[im] * 128 + ((ch ^ asw[im]) << 4));
            #pragma unroll
            for (int ib = 0; ib < 2; ib++) {
                int row = kk * 16 + rlo;
                int cb = (wn >> 3) + ib * 2 + chi;
                ldm_x4t(b[ib], b_s + row * 128 + ((cb ^ (row & 7)) << 4));
            }
            #pragma unroll
            for (int im = 0; im < 2; im++) {
                mma_bf16(acc[im][0], a[im], b[0][0], b[0][1]);
                mma_bf16(acc[im][1], a[im], b[0][2], b[0][3]);
                mma_bf16(acc[im][2], a[im], b[1][0], b[1][1]);
                mma_bf16(acc[im][3], a[im], b[1][2], b[1][3]);
            }
        }
    };

    load_stage(0, 0);
    load_stage(1, 1);
    #pragma unroll 1
    for (int ki = 0; ki < 16; ki++) {
        if (ki < 15) cp_wait<1>(); else cp_wait<0>();
        __syncthreads();
        if (ki + 2 < 16) load_stage(ki + 2, (ki + 2) % 3);
        compute(ki % 3);
    }

    // ---- bias fold: one extra k16 step with A'=e(bf16), B'=bvec^T ----
    {
        uint32_t b[2][4];
        #pragma unroll
        for (int ib = 0; ib < 2; ib++) {
            int row = wn + ib * 16 + rlo;
            ldm_x4(b[ib], Be_base + row * 48 + chi * 16);
        }
        #pragma unroll
        for (int im = 0; im < 2; im++) {
            uint32_t a[4];
            int row = wm + im * 16 + rlo;
            ldm_x4(a, Ae_base + row * 48 + chi * 16);
            mma_bf16(acc[im][0], a, b[0][0], b[0][2]);
            mma_bf16(acc[im][1], a, b[0][1], b[0][3]);
            mma_bf16(acc[im][2], a, b[1][0], b[1][2]);
            mma_bf16(acc[im][3], a, b[1][1], b[1][3]);
        }
    }

    // epilogue: divide by Z, store
    const int qr = lane >> 2;
    const int qc = (lane & 3) * 2;
    #pragma unroll
    for (int im = 0; im < 2; im++) {
        int r0g = m0 + wm + im * 16 + qr;
        float zi0 = 1.0f / g_Z[r0g];
        float zi1 = 1.0f / g_Z[r0g + 8];
        #pragma unroll
        for (int in = 0; in < 4; in++) {
            int cg = n0 + wn + in * 8 + qc;
            float* c = acc[im][in];
            float2 v0 = {c[0] * zi0, c[1] * zi0};
            float2 v1 = {c[2] * zi1, c[3] * zi1};
            *(float2*)&out[(size_t)r0g * NU + cg] = v0;
            *(float2*)&out[(size_t)(r0g + 8) * NU + cg] = v1;
        }
    }
}

// ============================================================
extern "C" void kernel_launch(void* const* d_in, const int* in_sizes, int n_in,
                              void* d_out, int out_size) {
    const float* h    = (const float*)d_in[0];   // [B, F]
    const float* dom  = (const float*)d_in[1];   // [J, M, F]
    const float* W    = (const float*)d_in[2];   // [J, M, U]
    const float* bvec = (const float*)d_in[3];   // [J, U]
    float* out = (float*)d_out;                  // [B, U]

    cudaFuncSetAttribute(kdd_kernel,   cudaFuncAttributeMaxDynamicSharedMemorySize, 65536);
    cudaFuncSetAttribute(gemm1_kernel, cudaFuncAttributeMaxDynamicSharedMemorySize, 49152);
    cudaFuncSetAttribute(gemm2_kernel, cudaFuncAttributeMaxDynamicSharedMemorySize, 82944);

    prep_kernel<<<(BATCH + 2 * JM) / 8, 256>>>(h, dom, W);
    kdd_kernel<<<NJ, 128, 65536>>>();
    gemm1_kernel<<<dim3(JM / 128, BATCH / 128), 256, 49152>>>();
    gemm2_kernel<<<dim3(NU / 64, BATCH / 128), 256, 82944>>>(bvec, out);
}

// round 9
// speedup vs baseline: 1.5117x; 1.0078x over previous
#include <cuda_runtime.h>
#include <cuda_bf16.h>
#include <math.h>
#include <stdint.h>

#define BATCH 4096
#define FDIM  512
#define NJ    16
#define NM    64
#define NU    512
#define JM    (NJ*NM)   // 1024

// ---- scratch (device globals; no allocation allowed) ----
__device__ __nv_bfloat16 g_hb[(size_t)BATCH * FDIM];   // 4 MB
__device__ __nv_bfloat16 g_db[(size_t)JM * FDIM];      // 1 MB
__device__ __nv_bfloat16 g_Wb[(size_t)JM * NU];        // 1 MB
__device__ __nv_bfloat16 g_A2[(size_t)BATCH * JM];     // 8 MB : e-scaled Khd
__device__ float g_h2[BATCH];
__device__ float g_d2[JM];
__device__ float g_kdd[NJ];
__device__ float g_e[BATCH * NJ];
__device__ float g_Z[BATCH];

// ================= PTX helpers =================
__device__ __forceinline__ void cp16(uint32_t dst, const void* src) {
    asm volatile("cp.async.cg.shared.global [%0], [%1], 16;\n" :: "r"(dst), "l"(src));
}
__device__ __forceinline__ void cp_commit() { asm volatile("cp.async.commit_group;\n"); }
template <int N> __device__ __forceinline__ void cp_wait() {
    asm volatile("cp.async.wait_group %0;\n" :: "n"(N));
}
__device__ __forceinline__ void ldm_x4(uint32_t a[4], uint32_t addr) {
    asm volatile("ldmatrix.sync.aligned.m8n8.x4.shared.b16 {%0,%1,%2,%3}, [%4];\n"
                 : "=r"(a[0]), "=r"(a[1]), "=r"(a[2]), "=r"(a[3]) : "r"(addr));
}
__device__ __forceinline__ void ldm_x4t(uint32_t a[4], uint32_t addr) {
    asm volatile("ldmatrix.sync.aligned.m8n8.x4.trans.shared.b16 {%0,%1,%2,%3}, [%4];\n"
                 : "=r"(a[0]), "=r"(a[1]), "=r"(a[2]), "=r"(a[3]) : "r"(addr));
}
__device__ __forceinline__ void mma_bf16(float c[4], const uint32_t a[4], uint32_t b0, uint32_t b1) {
    asm volatile(
        "mma.sync.aligned.m16n8k16.row.col.f32.bf16.bf16.f32 "
        "{%0,%1,%2,%3}, {%4,%5,%6,%7}, {%8,%9}, {%0,%1,%2,%3};\n"
        : "+f"(c[0]), "+f"(c[1]), "+f"(c[2]), "+f"(c[3])
        : "r"(a[0]), "r"(a[1]), "r"(a[2]), "r"(a[3]), "r"(b0), "r"(b1));
}

// ========== merged prep + kdd (one launch, independent halves) ===========
// blocks [0, NJ): kdd for domain j (converts its own rows from fp32)
// blocks [NJ, NJ+768): warp-per-row convert/sumsq for h, dom, W
__global__ void __launch_bounds__(256) prep_kdd_kernel(const float* __restrict__ h,
                                                       const float* __restrict__ dom,
                                                       const float* __restrict__ W) {
    extern __shared__ char smem[];           // 64 KB bf16 staging (kdd blocks only)
    __shared__ float d2s[NM];
    __shared__ float ws[4];
    const int bid = blockIdx.x;
    const int tid = threadIdx.x;
    const int lane = tid & 31, w = tid >> 5;

    if (bid < NJ) {
        // ---------------- kdd for j = bid ----------------
        const int j = bid;
        const float* dj = dom + (size_t)j * NM * FDIM;
        uint32_t base = (uint32_t)__cvta_generic_to_shared(smem);

        // convert rows [w*8, w*8+8) fp32 -> bf16 swizzled smem, plus row sumsq
        #pragma unroll
        for (int rr = 0; rr < 8; rr++) {
            int r = w * 8 + rr;
            const float* src = dj + (size_t)r * FDIM;
            float s = 0.f;
            #pragma unroll
            for (int t = 0; t < 2; t++) {
                int c = lane + t * 32;            // 16B chunk index, 0..63
                float4 v0 = *(const float4*)&src[c * 8];
                float4 v1 = *(const float4*)&src[c * 8 + 4];
                s += v0.x*v0.x + v0.y*v0.y + v0.z*v0.z + v0.w*v0.w
                   + v1.x*v1.x + v1.y*v1.y + v1.z*v1.z + v1.w*v1.w;
                __nv_bfloat162 p0 = __floats2bfloat162_rn(v0.x, v0.y);
                __nv_bfloat162 p1 = __floats2bfloat162_rn(v0.z, v0.w);
                __nv_bfloat162 p2 = __floats2bfloat162_rn(v1.x, v1.y);
                __nv_bfloat162 p3 = __floats2bfloat162_rn(v1.z, v1.w);
                uint4 u;
                u.x = *(uint32_t*)&p0; u.y = *(uint32_t*)&p1;
                u.z = *(uint32_t*)&p2; u.w = *(uint32_t*)&p3;
                *(uint4*)(smem + r * 1024 + ((c ^ (r & 7)) << 4)) = u;
            }
            #pragma unroll
            for (int off = 16; off; off >>= 1) s += __shfl_xor_sync(0xffffffffu, s, off);
            if (lane == 0) d2s[r] = s;
        }
        __syncthreads();

        // G = dj @ dj^T on tensor cores (warps 0-3 only)
        float acc[8][4] = {};
        const int rlo = lane & 15, chi = lane >> 4;
        if (w < 4) {
            #pragma unroll 4
            for (int kk = 0; kk < 32; kk++) {
                int ch = kk * 2 + chi;
                uint32_t a[4], b[4][4];
                {
                    int row = w * 16 + rlo;
                    ldm_x4(a, base + row * 1024 + ((ch ^ (row & 7)) << 4));
                }
                #pragma unroll
                for (int nb = 0; nb < 4; nb++) {
                    int row = nb * 16 + rlo;
                    ldm_x4(b[nb], base + row * 1024 + ((ch ^ (row & 7)) << 4));
                }
                #pragma unroll
                for (int nb = 0; nb < 4; nb++) {
                    mma_bf16(acc[2*nb],   a, b[nb][0], b[nb][2]);
                    mma_bf16(acc[2*nb+1], a, b[nb][1], b[nb][3]);
                }
            }
            const int qr = lane >> 2;
            const int qc = (lane & 3) * 2;
            int m0 = w * 16 + qr;
            float d2a = d2s[m0], d2b = d2s[m0 + 8];
            float s = 0.f;
            #pragma unroll
            for (int nt = 0; nt < 8; nt++) {
                int n = nt * 8 + qc;
                float d2x = d2s[n], d2y = d2s[n + 1];
                float* c = acc[nt];
                s += expf(-2.f * (d2a + d2x - 2.f * c[0]));
                s += expf(-2.f * (d2a + d2y - 2.f * c[1]));
                s += expf(-2.f * (d2b + d2x - 2.f * c[2]));
                s += expf(-2.f * (d2b + d2y - 2.f * c[3]));
            }
            #pragma unroll
            for (int off = 16; off; off >>= 1) s += __shfl_xor_sync(0xffffffffu, s, off);
            if (lane == 0) ws[w] = s;
        }
        __syncthreads();
        if (tid == 0) g_kdd[j] = (ws[0] + ws[1] + ws[2] + ws[3]) * (1.0f / (NM * NM));
    } else {
        // ---------------- prep: warp-per-row convert + sumsq ----------------
        int warp = (bid - NJ) * 8 + w;
        const float* p;
        __nv_bfloat16* dst;
        float* o = nullptr;
        if (warp < BATCH) {
            p = h + (size_t)warp * FDIM; dst = g_hb + (size_t)warp * FDIM; o = &g_h2[warp];
            if (lane == 0) g_Z[warp] = 0.f;
        } else if (warp < BATCH + JM) {
            int r = warp - BATCH;
            p = dom + (size_t)r * FDIM; dst = g_db + (size_t)r * FDIM; o = &g_d2[r];
        } else {
            int r = warp - BATCH - JM;
            p = W + (size_t)r * NU; dst = g_Wb + (size_t)r * NU;
        }
        float s = 0.f;
        #pragma unroll
        for (int i = 0; i < 4; i++) {
            int idx = (lane + i * 32) << 2;
            float4 v = *(const float4*)&p[idx];
            __nv_bfloat162 o0 = __floats2bfloat162_rn(v.x, v.y);
            __nv_bfloat162 o1 = __floats2bfloat162_rn(v.z, v.w);
            uint2 u; u.x = *(uint32_t*)&o0; u.y = *(uint32_t*)&o1;
            *(uint2*)&dst[idx] = u;
            s += v.x*v.x + v.y*v.y + v.z*v.z + v.w*v.w;
        }
        if (o) {
            #pragma unroll
            for (int off = 16; off; off >>= 1) s += __shfl_xor_sync(0xffffffffu, s, off);
            if (lane == 0) *o = s;
        }
    }
}

// ================= GEMM1: A2 = e * exp(4*h.domT - 2*(h2+d2)) =============
// 128x128 tile (=2 full domains), BK=32, 3-stage, 256 thr, 2 CTAs/SM.
__global__ void __launch_bounds__(256, 2) gemm1_kernel() {
    extern __shared__ char smem[];
    __shared__ float jp[128][2];
    __shared__ float es[128][2];
    __shared__ float kddm[2];
    const int tid = threadIdx.x;
    const int lane = tid & 31, wid = tid >> 5;
    const int wm = (wid >> 2) * 64;     // 2 m warps
    const int wn = (wid & 3) * 32;      // 4 n warps
    const int m0 = blockIdx.y * 128;
    const int n0 = blockIdx.x * 128;
    const int j0 = blockIdx.x * 2;

    uint32_t base = (uint32_t)__cvta_generic_to_shared(smem);

    if (tid < 256) { jp[tid >> 1][tid & 1] = 0.f; }
    if (tid < 2) kddm[tid] = g_kdd[j0 + tid];

    const int rlo = lane & 15, chi = lane >> 4;
    int arow[4], asw[4], brow[2], bsw[2];
    #pragma unroll
    for (int im = 0; im < 4; im++) { arow[im] = wm + im * 16 + rlo; asw[im] = (arow[im] >> 1) & 3; }
    #pragma unroll
    for (int ib = 0; ib < 2; ib++) { brow[ib] = wn + ib * 16 + rlo; bsw[ib] = (brow[ib] >> 1) & 3; }

    float acc[4][4][4] = {};

    auto load_stage = [&](int ki, int s) {
        const __nv_bfloat16* ha = g_hb + (size_t)m0 * FDIM + ki * 32;
        const __nv_bfloat16* da = g_db + (size_t)n0 * FDIM + ki * 32;
        uint32_t a_s = base + s * 16384;
        uint32_t b_s = a_s + 8192;
        #pragma unroll
        for (int i = 0; i < 2; i++) {
            int lin = tid + i * 256;
            int r = lin >> 2, c = lin & 3;
            uint32_t off = (uint32_t)(r * 64 + (((c ^ ((r >> 1) & 3))) << 4));
            cp16(a_s + off, ha + (size_t)r * FDIM + c * 8);
            cp16(b_s + off, da + (size_t)r * FDIM + c * 8);
        }
        cp_commit();
    };

    auto compute = [&](int s) {
        uint32_t a_s = base + s * 16384;
        uint32_t b_s = a_s + 8192;
        #pragma unroll
        for (int kk = 0; kk < 2; kk++) {
            int ch = kk * 2 + chi;
            uint32_t a[4][4], b[2][4];
            #pragma unroll
            for (int im = 0; im < 4; im++)
                ldm_x4(a[im], a_s + arow[im] * 64 + ((ch ^ asw[im]) << 4));
            #pragma unroll
            for (int ib = 0; ib < 2; ib++)
                ldm_x4(b[ib], b_s + brow[ib] * 64 + ((ch ^ bsw[ib]) << 4));
            #pragma unroll
            for (int im = 0; im < 4; im++) {
                mma_bf16(acc[im][0], a[im], b[0][0], b[0][2]);
                mma_bf16(acc[im][1], a[im], b[0][1], b[0][3]);
                mma_bf16(acc[im][2], a[im], b[1][0], b[1][2]);
                mma_bf16(acc[im][3], a[im], b[1][1], b[1][3]);
            }
        }
    };

    load_stage(0, 0);
    load_stage(1, 1);
    #pragma unroll 1
    for (int ki = 0; ki < 16; ki++) {
        if (ki < 15) cp_wait<1>(); else cp_wait<0>();
        __syncthreads();
        if (ki + 2 < 16) load_stage(ki + 2, (ki + 2) % 3);
        compute(ki % 3);
    }

    // ---- epilogue: exp, per-(row,j) sums, e, scale, store ----
    const int qr = lane >> 2;
    const int qc = (lane & 3) * 2;
    const int jj = wn >> 6;
    #pragma unroll
    for (int im = 0; im < 4; im++) {
        int r0g = m0 + wm + im * 16 + qr;
        float h2a = g_h2[r0g], h2b = g_h2[r0g + 8];
        float rs0 = 0.f, rs1 = 0.f;
        #pragma unroll
        for (int in = 0; in < 4; in++) {
            int cg = n0 + wn + in * 8 + qc;
            float d2x = g_d2[cg], d2y = g_d2[cg + 1];
            float* c = acc[im][in];
            c[0] = expf(4.f * c[0] - 2.f * (h2a + d2x));
            c[1] = expf(4.f * c[1] - 2.f * (h2a + d2y));
            c[2] = expf(4.f * c[2] - 2.f * (h2b + d2x));
            c[3] = expf(4.f * c[3] - 2.f * (h2b + d2y));
            rs0 += c[0] + c[1];
            rs1 += c[2] + c[3];
        }
        rs0 += __shfl_xor_sync(0xffffffffu, rs0, 1);
        rs0 += __shfl_xor_sync(0xffffffffu, rs0, 2);
        rs1 += __shfl_xor_sync(0xffffffffu, rs1, 1);
        rs1 += __shfl_xor_sync(0xffffffffu, rs1, 2);
        if ((lane & 3) == 0) {
            atomicAdd(&jp[wm + im * 16 + qr][jj], rs0);
            atomicAdd(&jp[wm + im * 16 + qr + 8][jj], rs1);
        }
    }
    __syncthreads();
    if (tid < 256) {
        int rl = tid >> 1, j = tid & 1;
        float jsum = jp[rl][j];
        float e = expf(jsum * (1.0f / 32.0f) - 1.0f - kddm[j]);
        es[rl][j] = e;
        g_e[(m0 + rl) * NJ + j0 + j] = e;
        atomicAdd(&g_Z[m0 + rl], e);
    }
    __syncthreads();
    #pragma unroll
    for (int im = 0; im < 4; im++) {
        int rl = wm + im * 16 + qr;
        int r0g = m0 + rl;
        float e0 = es[rl][jj], e1 = es[rl + 8][jj];
        #pragma unroll
        for (int in = 0; in < 4; in++) {
            int cg = n0 + wn + in * 8 + qc;
            float* c = acc[im][in];
            *(__nv_bfloat162*)&g_A2[(size_t)r0g * JM + cg] =
                __floats2bfloat162_rn(c[0] * e0, c[1] * e0);
            *(__nv_bfloat162*)&g_A2[(size_t)(r0g + 8) * JM + cg] =
                __floats2bfloat162_rn(c[2] * e1, c[3] * e1);
        }
    }
}

// ================= GEMM2: out = (A2 @ W + e @ bvec) / Z ==================
// 128x64 tile, BK=64, 3-stage, 256 threads (4m x 2n warps, warp 32x32),
// 2 CTAs/SM, fragment double-buffered inner loop.
__global__ void __launch_bounds__(256, 2) gemm2_kernel(const float* __restrict__ bvec,
                                                       float* __restrict__ out) {
    extern __shared__ char smem[];
    const int tid = threadIdx.x;
    const int lane = tid & 31, wid = tid >> 5;
    const int wm = (wid >> 1) * 32;    // 4 m bands of 32
    const int wn = (wid & 1) * 32;     // 2 n bands of 32
    const int m0 = blockIdx.y * 128;
    const int n0 = blockIdx.x * 64;

    uint32_t base = (uint32_t)__cvta_generic_to_shared(smem);
    uint32_t Bs_base = base + 49152;
    uint32_t Ae_base = base + 73728;
    uint32_t Be_base = base + 79872;
    __nv_bfloat16* Ae = (__nv_bfloat16*)(smem + 73728);
    __nv_bfloat16* Be = (__nv_bfloat16*)(smem + 79872);

    // stage e (bf16) and bvec^T (bf16)
    for (int idx = tid; idx < 128 * 16; idx += 256) {
        int rr = idx >> 4, j = idx & 15;
        Ae[rr * 24 + j] = __float2bfloat16(g_e[(size_t)(m0 + rr) * NJ + j]);
        if (rr < 64) Be[rr * 24 + j] = __float2bfloat16(bvec[(size_t)j * NU + n0 + rr]);
    }

    const int rlo = lane & 15, chi = lane >> 4;
    int arow[2], asw[2];
    #pragma unroll
    for (int im = 0; im < 2; im++) { arow[im] = wm + im * 16 + rlo; asw[im] = arow[im] & 7; }

    float acc[2][4][4] = {};

    auto load_stage = [&](int ki, int s) {
        const __nv_bfloat16* asrc = g_A2 + (size_t)m0 * JM + ki * 64;
        const __nv_bfloat16* bsrc = g_Wb + (size_t)ki * 64 * NU + n0;
        uint32_t a_s = base + s * 16384;
        uint32_t b_s = Bs_base + s * 8192;
        #pragma unroll
        for (int i = 0; i < 4; i++) {
            int lin = tid + i * 256;
            int r = lin >> 3, c = lin & 7;
            cp16(a_s + r * 128 + ((c ^ (r & 7)) << 4), asrc + (size_t)r * JM + c * 8);
        }
        #pragma unroll
        for (int i = 0; i < 2; i++) {
            int lin = tid + i * 256;
            int r = lin >> 3, c = lin & 7;
            cp16(b_s + r * 128 + ((c ^ (r & 7)) << 4), bsrc + (size_t)r * NU + c * 8);
        }
        cp_commit();
    };

    uint32_t fa[2][2][4], fb[2][2][4];
    auto ldfrag = [&](uint32_t a_s, uint32_t b_s, int kk, int buf) {
        int ch = kk * 2 + chi;
        #pragma unroll
        for (int im = 0; im < 2; im++)
            ldm_x4(fa[buf][im], a_s + arow[im] * 128 + ((ch ^ asw[im]) << 4));
        #pragma unroll
        for (int ib = 0; ib < 2; ib++) {
            int row = kk * 16 + rlo;
            int cb = (wn >> 3) + ib * 2 + chi;
            ldm_x4t(fb[buf][ib], b_s + row * 128 + ((cb ^ (row & 7)) << 4));
        }
    };
    auto domma = [&](int buf) {
        #pragma unroll
        for (int im = 0; im < 2; im++) {
            mma_bf16(acc[im][0], fa[buf][im], fb[buf][0][0], fb[buf][0][1]);
            mma_bf16(acc[im][1], fa[buf][im], fb[buf][0][2], fb[buf][0][3]);
            mma_bf16(acc[im][2], fa[buf][im], fb[buf][1][0], fb[buf][1][1]);
            mma_bf16(acc[im][3], fa[buf][im], fb[buf][1][2], fb[buf][1][3]);
        }
    };
    auto compute = [&](int s) {
        uint32_t a_s = base + s * 16384;
        uint32_t b_s = Bs_base + s * 8192;
        ldfrag(a_s, b_s, 0, 0);
        #pragma unroll
        for (int kk = 0; kk < 4; kk++) {
            if (kk < 3) ldfrag(a_s, b_s, kk + 1, (kk + 1) & 1);
            domma(kk & 1);
        }
    };

    load_stage(0, 0);
    load_stage(1, 1);
    #pragma unroll 1
    for (int ki = 0; ki < 16; ki++) {
        if (ki < 15) cp_wait<1>(); else cp_wait<0>();
        __syncthreads();
        if (ki + 2 < 16) load_stage(ki + 2, (ki + 2) % 3);
        compute(ki % 3);
    }

    // ---- bias fold: one extra k16 step with A'=e(bf16), B'=bvec^T ----
    {
        uint32_t b[2][4];
        #pragma unroll
        for (int ib = 0; ib < 2; ib++) {
            int row = wn + ib * 16 + rlo;
            ldm_x4(b[ib], Be_base + row * 48 + chi * 16);
        }
        #pragma unroll
        for (int im = 0; im < 2; im++) {
            uint32_t a[4];
            int row = wm + im * 16 + rlo;
            ldm_x4(a, Ae_base + row * 48 + chi * 16);
            mma_bf16(acc[im][0], a, b[0][0], b[0][2]);
            mma_bf16(acc[im][1], a, b[0][1], b[0][3]);
            mma_bf16(acc[im][2], a, b[1][0], b[1][2]);
            mma_bf16(acc[im][3], a, b[1][1], b[1][3]);
        }
    }

    // epilogue: divide by Z, store
    const int qr = lane >> 2;
    const int qc = (lane & 3) * 2;
    #pragma unroll
    for (int im = 0; im < 2; im++) {
        int r0g = m0 + wm + im * 16 + qr;
        float zi0 = 1.0f / g_Z[r0g];
        float zi1 = 1.0f / g_Z[r0g + 8];
        #pragma unroll
        for (int in = 0; in < 4; in++) {
            int cg = n0 + wn + in * 8 + qc;
            float* c = acc[im][in];
            float2 v0 = {c[0] * zi0, c[1] * zi0};
            float2 v1 = {c[2] * zi1, c[3] * zi1};
            *(float2*)&out[(size_t)r0g * NU + cg] = v0;
            *(float2*)&out[(size_t)(r0g + 8) * NU + cg] = v1;
        }
    }
}

// ============================================================
extern "C" void kernel_launch(void* const* d_in, const int* in_sizes, int n_in,
                              void* d_out, int out_size) {
    const float* h    = (const float*)d_in[0];   // [B, F]
    const float* dom  = (const float*)d_in[1];   // [J, M, F]
    const float* W    = (const float*)d_in[2];   // [J, M, U]
    const float* bvec = (const float*)d_in[3];   // [J, U]
    float* out = (float*)d_out;                  // [B, U]

    cudaFuncSetAttribute(prep_kdd_kernel, cudaFuncAttributeMaxDynamicSharedMemorySize, 65536);
    cudaFuncSetAttribute(gemm1_kernel,    cudaFuncAttributeMaxDynamicSharedMemorySize, 49152);
    cudaFuncSetAttribute(gemm2_kernel,    cudaFuncAttributeMaxDynamicSharedMemorySize, 82944);

    prep_kdd_kernel<<<NJ + (BATCH + 2 * JM) / 8, 256, 65536>>>(h, dom, W);
    gemm1_kernel<<<dim3(JM / 128, BATCH / 128), 256, 49152>>>();
    gemm2_kernel<<<dim3(NU / 64, BATCH / 128), 256, 82944>>>(bvec, out);
}

// round 10
// speedup vs baseline: 1.5125x; 1.0006x over previous
#include <cuda_runtime.h>
#include <cuda_bf16.h>
#include <math.h>
#include <stdint.h>

#define BATCH 4096
#define FDIM  512
#define NJ    16
#define NM    64
#define NU    512
#define JM    (NJ*NM)   // 1024

// ---- scratch (device globals; no allocation allowed) ----
__device__ __nv_bfloat16 g_hb[(size_t)BATCH * FDIM];   // 4 MB
__device__ __nv_bfloat16 g_db[(size_t)JM * FDIM];      // 1 MB
__device__ __nv_bfloat16 g_Wb[(size_t)JM * NU];        // 1 MB
__device__ __nv_bfloat16 g_A2[(size_t)BATCH * JM];     // 8 MB : e-scaled Khd
__device__ float g_h2[BATCH];
__device__ float g_d2[JM];
__device__ float g_kdd[NJ];
__device__ float g_e[BATCH * NJ];
__device__ float g_Z[BATCH];

// ================= PTX helpers =================
__device__ __forceinline__ void cp16(uint32_t dst, const void* src) {
    asm volatile("cp.async.cg.shared.global [%0], [%1], 16;\n" :: "r"(dst), "l"(src));
}
__device__ __forceinline__ void cp_commit() { asm volatile("cp.async.commit_group;\n"); }
template <int N> __device__ __forceinline__ void cp_wait() {
    asm volatile("cp.async.wait_group %0;\n" :: "n"(N));
}
__device__ __forceinline__ void ldm_x4(uint32_t a[4], uint32_t addr) {
    asm volatile("ldmatrix.sync.aligned.m8n8.x4.shared.b16 {%0,%1,%2,%3}, [%4];\n"
                 : "=r"(a[0]), "=r"(a[1]), "=r"(a[2]), "=r"(a[3]) : "r"(addr));
}
__device__ __forceinline__ void ldm_x4t(uint32_t a[4], uint32_t addr) {
    asm volatile("ldmatrix.sync.aligned.m8n8.x4.trans.shared.b16 {%0,%1,%2,%3}, [%4];\n"
                 : "=r"(a[0]), "=r"(a[1]), "=r"(a[2]), "=r"(a[3]) : "r"(addr));
}
__device__ __forceinline__ void mma_bf16(float c[4], const uint32_t a[4], uint32_t b0, uint32_t b1) {
    asm volatile(
        "mma.sync.aligned.m16n8k16.row.col.f32.bf16.bf16.f32 "
        "{%0,%1,%2,%3}, {%4,%5,%6,%7}, {%8,%9}, {%0,%1,%2,%3};\n"
        : "+f"(c[0]), "+f"(c[1]), "+f"(c[2]), "+f"(c[3])
        : "r"(a[0]), "r"(a[1]), "r"(a[2]), "r"(a[3]), "r"(b0), "r"(b1));
}

// ========== merged prep + kdd (one launch, 32KB dynamic smem) ============
// blocks [0, NJ): kdd for domain j (two K=256 passes over 32KB staging)
// blocks [NJ, NJ+768): warp-per-row convert/sumsq for h, dom, W
__global__ void __launch_bounds__(256) prep_kdd_kernel(const float* __restrict__ h,
                                                       const float* __restrict__ dom,
                                                       const float* __restrict__ W) {
    extern __shared__ char smem[];           // 32 KB bf16 staging (kdd blocks only)
    __shared__ float d2s[NM];
    __shared__ float ws[4];
    const int bid = blockIdx.x;
    const int tid = threadIdx.x;
    const int lane = tid & 31, w = tid >> 5;

    if (bid < NJ) {
        // ---------------- kdd for j = bid ----------------
        const int j = bid;
        const float* dj = dom + (size_t)j * NM * FDIM;
        uint32_t base = (uint32_t)__cvta_generic_to_shared(smem);
        const int rlo = lane & 15, chi = lane >> 4;

        float acc[8][4] = {};
        float rs[8] = {};

        #pragma unroll 1
        for (int pass = 0; pass < 2; pass++) {
            // convert rows [w*8, w*8+8), cols [pass*256, pass*256+256) -> smem
            // smem row stride 512B = 32 chunks of 16B
            #pragma unroll
            for (int rr = 0; rr < 8; rr++) {
                int r = w * 8 + rr;
                const float* src = dj + (size_t)r * FDIM + pass * 256;
                int c = lane;                     // chunk 0..31
                float4 v0 = *(const float4*)&src[c * 8];
                float4 v1 = *(const float4*)&src[c * 8 + 4];
                rs[rr] += v0.x*v0.x + v0.y*v0.y + v0.z*v0.z + v0.w*v0.w
                        + v1.x*v1.x + v1.y*v1.y + v1.z*v1.z + v1.w*v1.w;
                __nv_bfloat162 p0 = __floats2bfloat162_rn(v0.x, v0.y);
                __nv_bfloat162 p1 = __floats2bfloat162_rn(v0.z, v0.w);
                __nv_bfloat162 p2 = __floats2bfloat162_rn(v1.x, v1.y);
                __nv_bfloat162 p3 = __floats2bfloat162_rn(v1.z, v1.w);
                uint4 u;
                u.x = *(uint32_t*)&p0; u.y = *(uint32_t*)&p1;
                u.z = *(uint32_t*)&p2; u.w = *(uint32_t*)&p3;
                *(uint4*)(smem + r * 512 + ((c ^ (r & 7)) << 4)) = u;
            }
            __syncthreads();

            // G += dj[:, pass] @ dj[:, pass]^T (warps 0-3)
            if (w < 4) {
                #pragma unroll 4
                for (int kk = 0; kk < 16; kk++) {
                    int ch = kk * 2 + chi;
                    uint32_t a[4], b[4][4];
                    {
                        int row = w * 16 + rlo;
                        ldm_x4(a, base + row * 512 + ((ch ^ (row & 7)) << 4));
                    }
                    #pragma unroll
                    for (int nb = 0; nb < 4; nb++) {
                        int row = nb * 16 + rlo;
                        ldm_x4(b[nb], base + row * 512 + ((ch ^ (row & 7)) << 4));
                    }
                    #pragma unroll
                    for (int nb = 0; nb < 4; nb++) {
                        mma_bf16(acc[2*nb],   a, b[nb][0], b[nb][2]);
                        mma_bf16(acc[2*nb+1], a, b[nb][1], b[nb][3]);
                    }
                }
            }
            __syncthreads();
        }

        // row sumsq -> d2s
        #pragma unroll
        for (int rr = 0; rr < 8; rr++) {
            float s = rs[rr];
            #pragma unroll
            for (int off = 16; off; off >>= 1) s += __shfl_xor_sync(0xffffffffu, s, off);
            if (lane == 0) d2s[w * 8 + rr] = s;
        }
        __syncthreads();

        // epilogue: exp + reduce (warps 0-3)
        if (w < 4) {
            const int qr = lane >> 2;
            const int qc = (lane & 3) * 2;
            int m0 = w * 16 + qr;
            float d2a = d2s[m0], d2b = d2s[m0 + 8];
            float s = 0.f;
            #pragma unroll
            for (int nt = 0; nt < 8; nt++) {
                int n = nt * 8 + qc;
                float d2x = d2s[n], d2y = d2s[n + 1];
                float* c = acc[nt];
                s += expf(-2.f * (d2a + d2x - 2.f * c[0]));
                s += expf(-2.f * (d2a + d2y - 2.f * c[1]));
                s += expf(-2.f * (d2b + d2x - 2.f * c[2]));
                s += expf(-2.f * (d2b + d2y - 2.f * c[3]));
            }
            #pragma unroll
            for (int off = 16; off; off >>= 1) s += __shfl_xor_sync(0xffffffffu, s, off);
            if (lane == 0) ws[w] = s;
        }
        __syncthreads();
        if (tid == 0) g_kdd[j] = (ws[0] + ws[1] + ws[2] + ws[3]) * (1.0f / (NM * NM));
    } else {
        // ---------------- prep: warp-per-row convert + sumsq ----------------
        int warp = (bid - NJ) * 8 + w;
        const float* p;
        __nv_bfloat16* dst;
        float* o = nullptr;
        if (warp < BATCH) {
            p = h + (size_t)warp * FDIM; dst = g_hb + (size_t)warp * FDIM; o = &g_h2[warp];
            if (lane == 0) g_Z[warp] = 0.f;
        } else if (warp < BATCH + JM) {
            int r = warp - BATCH;
            p = dom + (size_t)r * FDIM; dst = g_db + (size_t)r * FDIM; o = &g_d2[r];
        } else {
            int r = warp - BATCH - JM;
            p = W + (size_t)r * NU; dst = g_Wb + (size_t)r * NU;
        }
        float s = 0.f;
        #pragma unroll
        for (int i = 0; i < 4; i++) {
            int idx = (lane + i * 32) << 2;
            float4 v = *(const float4*)&p[idx];
            __nv_bfloat162 o0 = __floats2bfloat162_rn(v.x, v.y);
            __nv_bfloat162 o1 = __floats2bfloat162_rn(v.z, v.w);
            uint2 u; u.x = *(uint32_t*)&o0; u.y = *(uint32_t*)&o1;
            *(uint2*)&dst[idx] = u;
            s += v.x*v.x + v.y*v.y + v.z*v.z + v.w*v.w;
        }
        if (o) {
            #pragma unroll
            for (int off = 16; off; off >>= 1) s += __shfl_xor_sync(0xffffffffu, s, off);
            if (lane == 0) *o = s;
        }
    }
}

// ================= GEMM1: A2 = e * exp(4*h.domT - 2*(h2+d2)) =============
// 128x128 tile (=2 full domains), BK=32, 3-stage, 256 thr, 2 CTAs/SM.
__global__ void __launch_bounds__(256, 2) gemm1_kernel() {
    extern __shared__ char smem[];
    __shared__ float jp[128][2];
    __shared__ float es[128][2];
    __shared__ float kddm[2];
    const int tid = threadIdx.x;
    const int lane = tid & 31, wid = tid >> 5;
    const int wm = (wid >> 2) * 64;     // 2 m warps
    const int wn = (wid & 3) * 32;      // 4 n warps
    const int m0 = blockIdx.y * 128;
    const int n0 = blockIdx.x * 128;
    const int j0 = blockIdx.x * 2;

    uint32_t base = (uint32_t)__cvta_generic_to_shared(smem);

    if (tid < 256) { jp[tid >> 1][tid & 1] = 0.f; }
    if (tid < 2) kddm[tid] = g_kdd[j0 + tid];

    const int rlo = lane & 15, chi = lane >> 4;
    int arow[4], asw[4], brow[2], bsw[2];
    #pragma unroll
    for (int im = 0; im < 4; im++) { arow[im] = wm + im * 16 + rlo; asw[im] = (arow[im] >> 1) & 3; }
    #pragma unroll
    for (int ib = 0; ib < 2; ib++) { brow[ib] = wn + ib * 16 + rlo; bsw[ib] = (brow[ib] >> 1) & 3; }

    float acc[4][4][4] = {};

    auto load_stage = [&](int ki, int s) {
        const __nv_bfloat16* ha = g_hb + (size_t)m0 * FDIM + ki * 32;
        const __nv_bfloat16* da = g_db + (size_t)n0 * FDIM + ki * 32;
        uint32_t a_s = base + s * 16384;
        uint32_t b_s = a_s + 8192;
        #pragma unroll
        for (int i = 0; i < 2; i++) {
            int lin = tid + i * 256;
            int r = lin >> 2, c = lin & 3;
            uint32_t off = (uint32_t)(r * 64 + (((c ^ ((r >> 1) & 3))) << 4));
            cp16(a_s + off, ha + (size_t)r * FDIM + c * 8);
            cp16(b_s + off, da + (size_t)r * FDIM + c * 8);
        }
        cp_commit();
    };

    auto compute = [&](int s) {
        uint32_t a_s = base + s * 16384;
        uint32_t b_s = a_s + 8192;
        #pragma unroll
        for (int kk = 0; kk < 2; kk++) {
            int ch = kk * 2 + chi;
            uint32_t a[4][4], b[2][4];
            #pragma unroll
            for (int im = 0; im < 4; im++)
                ldm_x4(a[im], a_s + arow[im] * 64 + ((ch ^ asw[im]) << 4));
            #pragma unroll
            for (int ib = 0; ib < 2; ib++)
                ldm_x4(b[ib], b_s + brow[ib] * 64 + ((ch ^ bsw[ib]) << 4));
            #pragma unroll
            for (int im = 0; im < 4; im++) {
                mma_bf16(acc[im][0], a[im], b[0][0], b[0][2]);
                mma_bf16(acc[im][1], a[im], b[0][1], b[0][3]);
                mma_bf16(acc[im][2], a[im], b[1][0], b[1][2]);
                mma_bf16(acc[im][3], a[im], b[1][1], b[1][3]);
            }
        }
    };

    load_stage(0, 0);
    load_stage(1, 1);
    #pragma unroll 1
    for (int ki = 0; ki < 16; ki++) {
        if (ki < 15) cp_wait<1>(); else cp_wait<0>();
        __syncthreads();
        if (ki + 2 < 16) load_stage(ki + 2, (ki + 2) % 3);
        compute(ki % 3);
    }

    // ---- epilogue: exp, per-(row,j) sums, e, scale, store ----
    const int qr = lane >> 2;
    const int qc = (lane & 3) * 2;
    const int jj = wn >> 6;
    #pragma unroll
    for (int im = 0; im < 4; im++) {
        int r0g = m0 + wm + im * 16 + qr;
        float h2a = g_h2[r0g], h2b = g_h2[r0g + 8];
        float rs0 = 0.f, rs1 = 0.f;
        #pragma unroll
        for (int in = 0; in < 4; in++) {
            int cg = n0 + wn + in * 8 + qc;
            float d2x = g_d2[cg], d2y = g_d2[cg + 1];
            float* c = acc[im][in];
            c[0] = expf(4.f * c[0] - 2.f * (h2a + d2x));
            c[1] = expf(4.f * c[1] - 2.f * (h2a + d2y));
            c[2] = expf(4.f * c[2] - 2.f * (h2b + d2x));
            c[3] = expf(4.f * c[3] - 2.f * (h2b + d2y));
            rs0 += c[0] + c[1];
            rs1 += c[2] + c[3];
        }
        rs0 += __shfl_xor_sync(0xffffffffu, rs0, 1);
        rs0 += __shfl_xor_sync(0xffffffffu, rs0, 2);
        rs1 += __shfl_xor_sync(0xffffffffu, rs1, 1);
        rs1 += __shfl_xor_sync(0xffffffffu, rs1, 2);
        if ((lane & 3) == 0) {
            atomicAdd(&jp[wm + im * 16 + qr][jj], rs0);
            atomicAdd(&jp[wm + im * 16 + qr + 8][jj], rs1);
        }
    }
    __syncthreads();
    if (tid < 256) {
        int rl = tid >> 1, j = tid & 1;
        float jsum = jp[rl][j];
        float e = expf(jsum * (1.0f / 32.0f) - 1.0f - kddm[j]);
        es[rl][j] = e;
        g_e[(m0 + rl) * NJ + j0 + j] = e;
        atomicAdd(&g_Z[m0 + rl], e);
    }
    __syncthreads();
    #pragma unroll
    for (int im = 0; im < 4; im++) {
        int rl = wm + im * 16 + qr;
        int r0g = m0 + rl;
        float e0 = es[rl][jj], e1 = es[rl + 8][jj];
        #pragma unroll
        for (int in = 0; in < 4; in++) {
            int cg = n0 + wn + in * 8 + qc;
            float* c = acc[im][in];
            *(__nv_bfloat162*)&g_A2[(size_t)r0g * JM + cg] =
                __floats2bfloat162_rn(c[0] * e0, c[1] * e0);
            *(__nv_bfloat162*)&g_A2[(size_t)(r0g + 8) * JM + cg] =
                __floats2bfloat162_rn(c[2] * e1, c[3] * e1);
        }
    }
}

// ================= GEMM2: out = (A2 @ W + e @ bvec) / Z ==================
// 128x64 tile, BK=64, 3-stage, 256 threads (4m x 2n warps, warp 32x32),
// 2 CTAs/SM, fragment double-buffered inner loop.
__global__ void __launch_bounds__(256, 2) gemm2_kernel(const float* __restrict__ bvec,
                                                       float* __restrict__ out) {
    extern __shared__ char smem[];
    const int tid = threadIdx.x;
    const int lane = tid & 31, wid = tid >> 5;
    const int wm = (wid >> 1) * 32;    // 4 m bands of 32
    const int wn = (wid & 1) * 32;     // 2 n bands of 32
    const int m0 = blockIdx.y * 128;
    const int n0 = blockIdx.x * 64;

    uint32_t base = (uint32_t)__cvta_generic_to_shared(smem);
    uint32_t Bs_base = base + 49152;
    uint32_t Ae_base = base + 73728;
    uint32_t Be_base = base + 79872;
    __nv_bfloat16* Ae = (__nv_bfloat16*)(smem + 73728);
    __nv_bfloat16* Be = (__nv_bfloat16*)(smem + 79872);

    // stage e (bf16) and bvec^T (bf16)
    for (int idx = tid; idx < 128 * 16; idx += 256) {
        int rr = idx >> 4, j = idx & 15;
        Ae[rr * 24 + j] = __float2bfloat16(g_e[(size_t)(m0 + rr) * NJ + j]);
        if (rr < 64) Be[rr * 24 + j] = __float2bfloat16(bvec[(size_t)j * NU + n0 + rr]);
    }

    const int rlo = lane & 15, chi = lane >> 4;
    int arow[2], asw[2];
    #pragma unroll
    for (int im = 0; im < 2; im++) { arow[im] = wm + im * 16 + rlo; asw[im] = arow[im] & 7; }

    float acc[2][4][4] = {};

    auto load_stage = [&](int ki, int s) {
        const __nv_bfloat16* asrc = g_A2 + (size_t)m0 * JM + ki * 64;
        const __nv_bfloat16* bsrc = g_Wb + (size_t)ki * 64 * NU + n0;
        uint32_t a_s = base + s * 16384;
        uint32_t b_s = Bs_base + s * 8192;
        #pragma unroll
        for (int i = 0; i < 4; i++) {
            int lin = tid + i * 256;
            int r = lin >> 3, c = lin & 7;
            cp16(a_s + r * 128 + ((c ^ (r & 7)) << 4), asrc + (size_t)r * JM + c * 8);
        }
        #pragma unroll
        for (int i = 0; i < 2; i++) {
            int lin = tid + i * 256;
            int r = lin >> 3, c = lin & 7;
            cp16(b_s + r * 128 + ((c ^ (r & 7)) << 4), bsrc + (size_t)r * NU + c * 8);
        }
        cp_commit();
    };

    uint32_t fa[2][2][4], fb[2][2][4];
    auto ldfrag = [&](uint32_t a_s, uint32_t b_s, int kk, int buf) {
        int ch = kk * 2 + chi;
        #pragma unroll
        for (int im = 0; im < 2; im++)
            ldm_x4(fa[buf][im], a_s + arow[im] * 128 + ((ch ^ asw[im]) << 4));
        #pragma unroll
        for (int ib = 0; ib < 2; ib++) {
            int row = kk * 16 + rlo;
            int cb = (wn >> 3) + ib * 2 + chi;
            ldm_x4t(fb[buf][ib], b_s + row * 128 + ((cb ^ (row & 7)) << 4));
        }
    };
    auto domma = [&](int buf) {
        #pragma unroll
        for (int im = 0; im < 2; im++) {
            mma_bf16(acc[im][0], fa[buf][im], fb[buf][0][0], fb[buf][0][1]);
            mma_bf16(acc[im][1], fa[buf][im], fb[buf][0][2], fb[buf][0][3]);
            mma_bf16(acc[im][2], fa[buf][im], fb[buf][1][0], fb[buf][1][1]);
            mma_bf16(acc[im][3], fa[buf][im], fb[buf][1][2], fb[buf][1][3]);
        }
    };
    auto compute = [&](int s) {
        uint32_t a_s = base + s * 16384;
        uint32_t b_s = Bs_base + s * 8192;
        ldfrag(a_s, b_s, 0, 0);
        #pragma unroll
        for (int kk = 0; kk < 4; kk++) {
            if (kk < 3) ldfrag(a_s, b_s, kk + 1, (kk + 1) & 1);
            domma(kk & 1);
        }
    };

    load_stage(0, 0);
    load_stage(1, 1);
    #pragma unroll 1
    for (int ki = 0; ki < 16; ki++) {
        if (ki < 15) cp_wait<1>(); else cp_wait<0>();
        __syncthreads();
        if (ki + 2 < 16) load_stage(ki + 2, (ki + 2) % 3);
        compute(ki % 3);
    }

    // ---- bias fold: one extra k16 step with A'=e(bf16), B'=bvec^T ----
    {
        uint32_t b[2][4];
        #pragma unroll
        for (int ib = 0; ib < 2; ib++) {
            int row = wn + ib * 16 + rlo;
            ldm_x4(b[ib], Be_base + row * 48 + chi * 16);
        }
        #pragma unroll
        for (int im = 0; im < 2; im++) {
            uint32_t a[4];
            int row = wm + im * 16 + rlo;
            ldm_x4(a, Ae_base + row * 48 + chi * 16);
            mma_bf16(acc[im][0], a, b[0][0], b[0][2]);
            mma_bf16(acc[im][1], a, b[0][1], b[0][3]);
            mma_bf16(acc[im][2], a, b[1][0], b[1][2]);
            mma_bf16(acc[im][3], a, b[1][1], b[1][3]);
        }
    }

    // epilogue: divide by Z, store
    const int qr = lane >> 2;
    const int qc = (lane & 3) * 2;
    #pragma unroll
    for (int im = 0; im < 2; im++) {
        int r0g = m0 + wm + im * 16 + qr;
        float zi0 = 1.0f / g_Z[r0g];
        float zi1 = 1.0f / g_Z[r0g + 8];
        #pragma unroll
        for (int in = 0; in < 4; in++) {
            int cg = n0 + wn + in * 8 + qc;
            float* c = acc[im][in];
            float2 v0 = {c[0] * zi0, c[1] * zi0};
            float2 v1 = {c[2] * zi1, c[3] * zi1};
            *(float2*)&out[(size_t)r0g * NU + cg] = v0;
            *(float2*)&out[(size_t)(r0g + 8) * NU + cg] = v1;
        }
    }
}

// ============================================================
extern "C" void kernel_launch(void* const* d_in, const int* in_sizes, int n_in,
                              void* d_out, int out_size) {
    const float* h    = (const float*)d_in[0];   // [B, F]
    const float* dom  = (const float*)d_in[1];   // [J, M, F]
    const float* W    = (const float*)d_in[2];   // [J, M, U]
    const float* bvec = (const float*)d_in[3];   // [J, U]
    float* out = (float*)d_out;                  // [B, U]

    cudaFuncSetAttribute(prep_kdd_kernel, cudaFuncAttributeMaxDynamicSharedMemorySize, 32768);
    cudaFuncSetAttribute(gemm1_kernel,    cudaFuncAttributeMaxDynamicSharedMemorySize, 49152);
    cudaFuncSetAttribute(gemm2_kernel,    cudaFuncAttributeMaxDynamicSharedMemorySize, 82944);

    prep_kdd_kernel<<<NJ + (BATCH + 2 * JM) / 8, 256, 32768>>>(h, dom, W);
    gemm1_kernel<<<dim3(JM / 128, BATCH / 128), 256, 49152>>>();
    gemm2_kernel<<<dim3(NU / 64, BATCH / 128), 256, 82944>>>(bvec, out);
}

// round 11
// speedup vs baseline: 1.7385x; 1.1494x over previous
#include <cuda_runtime.h>
#include <cuda_bf16.h>
#include <math.h>
#include <stdint.h>

#define BATCH 4096
#define FDIM  512
#define NJ    16
#define NM    64
#define NU    512
#define JM    (NJ*NM)   // 1024

// ---- scratch (device globals; no allocation allowed) ----
__device__ __nv_bfloat16 g_hb[(size_t)BATCH * FDIM];   // 4 MB
__device__ __nv_bfloat16 g_db[(size_t)JM * FDIM];      // 1 MB
__device__ __nv_bfloat16 g_Wb[(size_t)JM * NU];        // 1 MB
__device__ __nv_bfloat16 g_A2[(size_t)BATCH * JM];     // 8 MB : e-scaled Khd
__device__ float g_h2[BATCH];
__device__ float g_d2[JM];
__device__ float g_kdd[NJ];
__device__ int   g_kdd_flag[NJ];
__device__ float g_e[BATCH * NJ];
__device__ float g_Z[BATCH];

// ================= PTX helpers =================
__device__ __forceinline__ void cp16(uint32_t dst, const void* src) {
    asm volatile("cp.async.cg.shared.global [%0], [%1], 16;\n" :: "r"(dst), "l"(src));
}
__device__ __forceinline__ void cp_commit() { asm volatile("cp.async.commit_group;\n"); }
template <int N> __device__ __forceinline__ void cp_wait() {
    asm volatile("cp.async.wait_group %0;\n" :: "n"(N));
}
__device__ __forceinline__ void ldm_x4(uint32_t a[4], uint32_t addr) {
    asm volatile("ldmatrix.sync.aligned.m8n8.x4.shared.b16 {%0,%1,%2,%3}, [%4];\n"
                 : "=r"(a[0]), "=r"(a[1]), "=r"(a[2]), "=r"(a[3]) : "r"(addr));
}
__device__ __forceinline__ void ldm_x4t(uint32_t a[4], uint32_t addr) {
    asm volatile("ldmatrix.sync.aligned.m8n8.x4.trans.shared.b16 {%0,%1,%2,%3}, [%4];\n"
                 : "=r"(a[0]), "=r"(a[1]), "=r"(a[2]), "=r"(a[3]) : "r"(addr));
}
__device__ __forceinline__ void mma_bf16(float c[4], const uint32_t a[4], uint32_t b0, uint32_t b1) {
    asm volatile(
        "mma.sync.aligned.m16n8k16.row.col.f32.bf16.bf16.f32 "
        "{%0,%1,%2,%3}, {%4,%5,%6,%7}, {%8,%9}, {%0,%1,%2,%3};\n"
        : "+f"(c[0]), "+f"(c[1]), "+f"(c[2]), "+f"(c[3])
        : "r"(a[0]), "r"(a[1]), "r"(a[2]), "r"(a[3]), "r"(b0), "r"(b1));
}

// ================= prep: pure streaming convert + sumsq + zero flags =====
// warp-per-row: rows [0,B)=h, [B,B+JM)=dom, [B+JM,B+2JM)=W
__global__ void __launch_bounds__(256) prep_kernel(const float* __restrict__ h,
                                                   const float* __restrict__ dom,
                                                   const float* __restrict__ W) {
    int warp = (blockIdx.x << 3) + (threadIdx.x >> 5);
    int lane = threadIdx.x & 31;
    if (blockIdx.x == 0 && threadIdx.x < NJ) g_kdd_flag[threadIdx.x] = 0;
    const float* p;
    __nv_bfloat16* dst;
    float* o = nullptr;
    if (warp < BATCH) {
        p = h + (size_t)warp * FDIM; dst = g_hb + (size_t)warp * FDIM; o = &g_h2[warp];
        if (lane == 0) g_Z[warp] = 0.f;
    } else if (warp < BATCH + JM) {
        int r = warp - BATCH;
        p = dom + (size_t)r * FDIM; dst = g_db + (size_t)r * FDIM; o = &g_d2[r];
    } else {
        int r = warp - BATCH - JM;
        p = W + (size_t)r * NU; dst = g_Wb + (size_t)r * NU;
    }
    float s = 0.f;
    #pragma unroll
    for (int i = 0; i < 4; i++) {
        int idx = (lane + i * 32) << 2;
        float4 v = *(const float4*)&p[idx];
        __nv_bfloat162 o0 = __floats2bfloat162_rn(v.x, v.y);
        __nv_bfloat162 o1 = __floats2bfloat162_rn(v.z, v.w);
        uint2 u; u.x = *(uint32_t*)&o0; u.y = *(uint32_t*)&o1;
        *(uint2*)&dst[idx] = u;
        s += v.x*v.x + v.y*v.y + v.z*v.z + v.w*v.w;
    }
    if (o) {
        #pragma unroll
        for (int off = 16; off; off >>= 1) s += __shfl_xor_sync(0xffffffffu, s, off);
        if (lane == 0) *o = s;
    }
}

// ====== GEMM1 launch: blocks [0,NJ) = kdd, blocks [NJ, NJ+256) = tiles ====
// kdd block j: G = dj @ dj^T from bf16 g_db (two K=256 passes, 32KB smem),
//              kdd[j] = mean exp(...); sets g_kdd_flag[j].
// tile blocks: 128x128 (=2 domains), BK=32, 3-stage; epilogue spin-waits
//              on g_kdd_flag, computes e, scales, stores A2 / e / Z.
__global__ void __launch_bounds__(256, 2) gemm1_kernel() {
    extern __shared__ char smem[];
    __shared__ float jp[128][2];
    __shared__ float es[128][2];
    __shared__ float kddm[2];
    __shared__ float d2s[NM];
    __shared__ float ws[4];
    const int bid = blockIdx.x;
    const int tid = threadIdx.x;
    const int lane = tid & 31, wid = tid >> 5;
    uint32_t base = (uint32_t)__cvta_generic_to_shared(smem);
    const int rlo = lane & 15, chi = lane >> 4;

    if (bid < NJ) {
        // ---------------- kdd block ----------------
        const int j = bid;
        const __nv_bfloat16* dj = g_db + (size_t)j * NM * FDIM;
        if (tid < NM) d2s[tid] = g_d2[j * NM + tid];
        float acc[8][4] = {};

        #pragma unroll 1
        for (int pass = 0; pass < 2; pass++) {
            // load 64 rows x 32 chunks (bf16, 512B/row) swizzled
            #pragma unroll
            for (int i = 0; i < 8; i++) {
                int lin = tid + i * 256;
                int r = lin >> 5, c = lin & 31;
                cp16(base + r * 512 + ((c ^ (r & 7)) << 4),
                     dj + (size_t)r * FDIM + pass * 256 + c * 8);
            }
            cp_commit();
            cp_wait<0>();
            __syncthreads();
            if (wid < 4) {
                #pragma unroll 4
                for (int kk = 0; kk < 16; kk++) {
                    int ch = kk * 2 + chi;
                    uint32_t a[4], b[4][4];
                    {
                        int row = wid * 16 + rlo;
                        ldm_x4(a, base + row * 512 + ((ch ^ (row & 7)) << 4));
                    }
                    #pragma unroll
                    for (int nb = 0; nb < 4; nb++) {
                        int row = nb * 16 + rlo;
                        ldm_x4(b[nb], base + row * 512 + ((ch ^ (row & 7)) << 4));
                    }
                    #pragma unroll
                    for (int nb = 0; nb < 4; nb++) {
                        mma_bf16(acc[2*nb],   a, b[nb][0], b[nb][2]);
                        mma_bf16(acc[2*nb+1], a, b[nb][1], b[nb][3]);
                    }
                }
            }
            __syncthreads();
        }

        if (wid < 4) {
            const int qr = lane >> 2;
            const int qc = (lane & 3) * 2;
            int m0 = wid * 16 + qr;
            float d2a = d2s[m0], d2b = d2s[m0 + 8];
            float s = 0.f;
            #pragma unroll
            for (int nt = 0; nt < 8; nt++) {
                int n = nt * 8 + qc;
                float d2x = d2s[n], d2y = d2s[n + 1];
                float* c = acc[nt];
                s += expf(-2.f * (d2a + d2x - 2.f * c[0]));
                s += expf(-2.f * (d2a + d2y - 2.f * c[1]));
                s += expf(-2.f * (d2b + d2x - 2.f * c[2]));
                s += expf(-2.f * (d2b + d2y - 2.f * c[3]));
            }
            #pragma unroll
            for (int off = 16; off; off >>= 1) s += __shfl_xor_sync(0xffffffffu, s, off);
            if (lane == 0) ws[wid] = s;
        }
        __syncthreads();
        if (tid == 0) {
            g_kdd[j] = (ws[0] + ws[1] + ws[2] + ws[3]) * (1.0f / (NM * NM));
            __threadfence();
            atomicExch(&g_kdd_flag[j], 1);
        }
        return;
    }

    // ---------------- gemm1 tile block ----------------
    const int t = bid - NJ;
    const int bx = t & 7, by = t >> 3;
    const int wm = (wid >> 2) * 64;     // 2 m warps
    const int wn = (wid & 3) * 32;      // 4 n warps
    const int m0 = by * 128;
    const int n0 = bx * 128;
    const int j0 = bx * 2;

    if (tid < 256) { jp[tid >> 1][tid & 1] = 0.f; }

    int arow[4], asw[4], brow[2], bsw[2];
    #pragma unroll
    for (int im = 0; im < 4; im++) { arow[im] = wm + im * 16 + rlo; asw[im] = (arow[im] >> 1) & 3; }
    #pragma unroll
    for (int ib = 0; ib < 2; ib++) { brow[ib] = wn + ib * 16 + rlo; bsw[ib] = (brow[ib] >> 1) & 3; }

    float acc[4][4][4] = {};

    auto load_stage = [&](int ki, int s) {
        const __nv_bfloat16* ha = g_hb + (size_t)m0 * FDIM + ki * 32;
        const __nv_bfloat16* da = g_db + (size_t)n0 * FDIM + ki * 32;
        uint32_t a_s = base + s * 16384;
        uint32_t b_s = a_s + 8192;
        #pragma unroll
        for (int i = 0; i < 2; i++) {
            int lin = tid + i * 256;
            int r = lin >> 2, c = lin & 3;
            uint32_t off = (uint32_t)(r * 64 + (((c ^ ((r >> 1) & 3))) << 4));
            cp16(a_s + off, ha + (size_t)r * FDIM + c * 8);
            cp16(b_s + off, da + (size_t)r * FDIM + c * 8);
        }
        cp_commit();
    };

    auto compute = [&](int s) {
        uint32_t a_s = base + s * 16384;
        uint32_t b_s = a_s + 8192;
        #pragma unroll
        for (int kk = 0; kk < 2; kk++) {
            int ch = kk * 2 + chi;
            uint32_t a[4][4], b[2][4];
            #pragma unroll
            for (int im = 0; im < 4; im++)
                ldm_x4(a[im], a_s + arow[im] * 64 + ((ch ^ asw[im]) << 4));
            #pragma unroll
            for (int ib = 0; ib < 2; ib++)
                ldm_x4(b[ib], b_s + brow[ib] * 64 + ((ch ^ bsw[ib]) << 4));
            #pragma unroll
            for (int im = 0; im < 4; im++) {
                mma_bf16(acc[im][0], a[im], b[0][0], b[0][2]);
                mma_bf16(acc[im][1], a[im], b[0][1], b[0][3]);
                mma_bf16(acc[im][2], a[im], b[1][0], b[1][2]);
                mma_bf16(acc[im][3], a[im], b[1][1], b[1][3]);
            }
        }
    };

    load_stage(0, 0);
    load_stage(1, 1);
    #pragma unroll 1
    for (int ki = 0; ki < 16; ki++) {
        if (ki < 15) cp_wait<1>(); else cp_wait<0>();
        __syncthreads();
        if (ki + 2 < 16) load_stage(ki + 2, (ki + 2) % 3);
        compute(ki % 3);
    }

    // ---- epilogue: exp, per-(row,j) sums, e, scale, store ----
    const int qr = lane >> 2;
    const int qc = (lane & 3) * 2;
    const int jj = wn >> 6;
    #pragma unroll
    for (int im = 0; im < 4; im++) {
        int r0g = m0 + wm + im * 16 + qr;
        float h2a = g_h2[r0g], h2b = g_h2[r0g + 8];
        float rs0 = 0.f, rs1 = 0.f;
        #pragma unroll
        for (int in = 0; in < 4; in++) {
            int cg = n0 + wn + in * 8 + qc;
            float d2x = g_d2[cg], d2y = g_d2[cg + 1];
            float* c = acc[im][in];
            c[0] = expf(4.f * c[0] - 2.f * (h2a + d2x));
            c[1] = expf(4.f * c[1] - 2.f * (h2a + d2y));
            c[2] = expf(4.f * c[2] - 2.f * (h2b + d2x));
            c[3] = expf(4.f * c[3] - 2.f * (h2b + d2y));
            rs0 += c[0] + c[1];
            rs1 += c[2] + c[3];
        }
        rs0 += __shfl_xor_sync(0xffffffffu, rs0, 1);
        rs0 += __shfl_xor_sync(0xffffffffu, rs0, 2);
        rs1 += __shfl_xor_sync(0xffffffffu, rs1, 1);
        rs1 += __shfl_xor_sync(0xffffffffu, rs1, 2);
        if ((lane & 3) == 0) {
            atomicAdd(&jp[wm + im * 16 + qr][jj], rs0);
            atomicAdd(&jp[wm + im * 16 + qr + 8][jj], rs1);
        }
    }
    // spin-wait for kdd values (kdd blocks are resident; wave-1 guaranteed)
    if (tid < 2) {
        while (atomicAdd(&g_kdd_flag[j0 + tid], 0) == 0) { }
        kddm[tid] = *((volatile float*)&g_kdd[j0 + tid]);
    }
    __syncthreads();
    if (tid < 256) {
        int rl = tid >> 1, j = tid & 1;
        float jsum = jp[rl][j];
        float e = expf(jsum * (1.0f / 32.0f) - 1.0f - kddm[j]);
        es[rl][j] = e;
        g_e[(m0 + rl) * NJ + j0 + j] = e;
        atomicAdd(&g_Z[m0 + rl], e);
    }
    __syncthreads();
    #pragma unroll
    for (int im = 0; im < 4; im++) {
        int rl = wm + im * 16 + qr;
        int r0g = m0 + rl;
        float e0 = es[rl][jj], e1 = es[rl + 8][jj];
        #pragma unroll
        for (int in = 0; in < 4; in++) {
            int cg = n0 + wn + in * 8 + qc;
            float* c = acc[im][in];
            *(__nv_bfloat162*)&g_A2[(size_t)r0g * JM + cg] =
                __floats2bfloat162_rn(c[0] * e0, c[1] * e0);
            *(__nv_bfloat162*)&g_A2[(size_t)(r0g + 8) * JM + cg] =
                __floats2bfloat162_rn(c[2] * e1, c[3] * e1);
        }
    }
}

// ================= GEMM2: out = (A2 @ W + e @ bvec) / Z ==================
// 128x64 tile, BK=64, 3-stage, 256 threads (4m x 2n warps, warp 32x32),
// 2 CTAs/SM, fragment double-buffered inner loop.
__global__ void __launch_bounds__(256, 2) gemm2_kernel(const float* __restrict__ bvec,
                                                       float* __restrict__ out) {
    extern __shared__ char smem[];
    const int tid = threadIdx.x;
    const int lane = tid & 31, wid = tid >> 5;
    const int wm = (wid >> 1) * 32;    // 4 m bands of 32
    const int wn = (wid & 1) * 32;     // 2 n bands of 32
    const int m0 = blockIdx.y * 128;
    const int n0 = blockIdx.x * 64;

    uint32_t base = (uint32_t)__cvta_generic_to_shared(smem);
    uint32_t Bs_base = base + 49152;
    uint32_t Ae_base = base + 73728;
    uint32_t Be_base = base + 79872;
    __nv_bfloat16* Ae = (__nv_bfloat16*)(smem + 73728);
    __nv_bfloat16* Be = (__nv_bfloat16*)(smem + 79872);

    // stage e (bf16) and bvec^T (bf16)
    for (int idx = tid; idx < 128 * 16; idx += 256) {
        int rr = idx >> 4, j = idx & 15;
        Ae[rr * 24 + j] = __float2bfloat16(g_e[(size_t)(m0 + rr) * NJ + j]);
        if (rr < 64) Be[rr * 24 + j] = __float2bfloat16(bvec[(size_t)j * NU + n0 + rr]);
    }

    const int rlo = lane & 15, chi = lane >> 4;
    int arow[2], asw[2];
    #pragma unroll
    for (int im = 0; im < 2; im++) { arow[im] = wm + im * 16 + rlo; asw[im] = arow[im] & 7; }

    float acc[2][4][4] = {};

    auto load_stage = [&](int ki, int s) {
        const __nv_bfloat16* asrc = g_A2 + (size_t)m0 * JM + ki * 64;
        const __nv_bfloat16* bsrc = g_Wb + (size_t)ki * 64 * NU + n0;
        uint32_t a_s = base + s * 16384;
        uint32_t b_s = Bs_base + s * 8192;
        #pragma unroll
        for (int i = 0; i < 4; i++) {
            int lin = tid + i * 256;
            int r = lin >> 3, c = lin & 7;
            cp16(a_s + r * 128 + ((c ^ (r & 7)) << 4), asrc + (size_t)r * JM + c * 8);
        }
        #pragma unroll
        for (int i = 0; i < 2; i++) {
            int lin = tid + i * 256;
            int r = lin >> 3, c = lin & 7;
            cp16(b_s + r * 128 + ((c ^ (r & 7)) << 4), bsrc + (size_t)r * NU + c * 8);
        }
        cp_commit();
    };

    uint32_t fa[2][2][4], fb[2][2][4];
    auto ldfrag = [&](uint32_t a_s, uint32_t b_s, int kk, int buf) {
        int ch = kk * 2 + chi;
        #pragma unroll
        for (int im = 0; im < 2; im++)
            ldm_x4(fa[buf][im], a_s + arow[im] * 128 + ((ch ^ asw[im]) << 4));
        #pragma unroll
        for (int ib = 0; ib < 2; ib++) {
            int row = kk * 16 + rlo;
            int cb = (wn >> 3) + ib * 2 + chi;
            ldm_x4t(fb[buf][ib], b_s + row * 128 + ((cb ^ (row & 7)) << 4));
        }
    };
    auto domma = [&](int buf) {
        #pragma unroll
        for (int im = 0; im < 2; im++) {
            mma_bf16(acc[im][0], fa[buf][im], fb[buf][0][0], fb[buf][0][1]);
            mma_bf16(acc[im][1], fa[buf][im], fb[buf][0][2], fb[buf][0][3]);
            mma_bf16(acc[im][2], fa[buf][im], fb[buf][1][0], fb[buf][1][1]);
            mma_bf16(acc[im][3], fa[buf][im], fb[buf][1][2], fb[buf][1][3]);
        }
    };
    auto compute = [&](int s) {
        uint32_t a_s = base + s * 16384;
        uint32_t b_s = Bs_base + s * 8192;
        ldfrag(a_s, b_s, 0, 0);
        #pragma unroll
        for (int kk = 0; kk < 4; kk++) {
            if (kk < 3) ldfrag(a_s, b_s, kk + 1, (kk + 1) & 1);
            domma(kk & 1);
        }
    };

    load_stage(0, 0);
    load_stage(1, 1);
    #pragma unroll 1
    for (int ki = 0; ki < 16; ki++) {
        if (ki < 15) cp_wait<1>(); else cp_wait<0>();
        __syncthreads();
        if (ki + 2 < 16) load_stage(ki + 2, (ki + 2) % 3);
        compute(ki % 3);
    }

    // ---- bias fold: one extra k16 step with A'=e(bf16), B'=bvec^T ----
    {
        uint32_t b[2][4];
        #pragma unroll
        for (int ib = 0; ib < 2; ib++) {
            int row = wn + ib * 16 + rlo;
            ldm_x4(b[ib], Be_base + row * 48 + chi * 16);
        }
        #pragma unroll
        for (int im = 0; im < 2; im++) {
            uint32_t a[4];
            int row = wm + im * 16 + rlo;
            ldm_x4(a, Ae_base + row * 48 + chi * 16);
            mma_bf16(acc[im][0], a, b[0][0], b[0][2]);
            mma_bf16(acc[im][1], a, b[0][1], b[0][3]);
            mma_bf16(acc[im][2], a, b[1][0], b[1][2]);
            mma_bf16(acc[im][3], a, b[1][1], b[1][3]);
        }
    }

    // epilogue: divide by Z, store
    const int qr = lane >> 2;
    const int qc = (lane & 3) * 2;
    #pragma unroll
    for (int im = 0; im < 2; im++) {
        int r0g = m0 + wm + im * 16 + qr;
        float zi0 = 1.0f / g_Z[r0g];
        float zi1 = 1.0f / g_Z[r0g + 8];
        #pragma unroll
        for (int in = 0; in < 4; in++) {
            int cg = n0 + wn + in * 8 + qc;
            float* c = acc[im][in];
            float2 v0 = {c[0] * zi0, c[1] * zi0};
            float2 v1 = {c[2] * zi1, c[3] * zi1};
            *(float2*)&out[(size_t)r0g * NU + cg] = v0;
            *(float2*)&out[(size_t)(r0g + 8) * NU + cg] = v1;
        }
    }
}

// ============================================================
extern "C" void kernel_launch(void* const* d_in, const int* in_sizes, int n_in,
                              void* d_out, int out_size) {
    const float* h    = (const float*)d_in[0];   // [B, F]
    const float* dom  = (const float*)d_in[1];   // [J, M, F]
    const float* W    = (const float*)d_in[2];   // [J, M, U]
    const float* bvec = (const float*)d_in[3];   // [J, U]
    float* out = (float*)d_out;                  // [B, U]

    cudaFuncSetAttribute(gemm1_kernel, cudaFuncAttributeMaxDynamicSharedMemorySize, 49152);
    cudaFuncSetAttribute(gemm2_kernel, cudaFuncAttributeMaxDynamicSharedMemorySize, 82944);

    prep_kernel<<<(BATCH + 2 * JM) / 8, 256>>>(h, dom, W);
    gemm1_kernel<<<NJ + (JM / 128) * (BATCH / 128), 256, 49152>>>();
    gemm2_kernel<<<dim3(NU / 64, BATCH / 128), 256, 82944>>>(bvec, out);
}